// round 5
// baseline (speedup 1.0000x reference)
#include <cuda_runtime.h>

#define EPSF 1e-5f

static constexpr int WAYN = 32;
static constexpr int QN   = 4096;
static constexpr int DIMN = 640;
static constexpr int RRN  = 10;

// ---------------- scratch (device globals; no allocation) ----------------
__device__ float g_protos[WAYN * DIMN];
__device__ float g_protosT[DIMN * WAYN];   // [k][w]
__device__ float g_pn[WAYN];
__device__ float g_part[16 * DIMN];
__device__ float g_c[WAYN];
__device__ float g_sp[WAYN];
__device__ float g_dis[WAYN * QN];
__device__ float g_T[WAYN];
__device__ float g_f10[WAYN];
__device__ float g_nid[WAYN * RRN];
__device__ int   g_nidx[WAYN * RRN];
__device__ float g_tmpT[DIMN * WAYN];      // [k][w]
__device__ float g_tn[WAYN];
__device__ float g_st[WAYN];

// ---------------- math helpers ----------------
__device__ __forceinline__ float expmap_scale(float nx, float c) {
    float sc = sqrtf(c);
    float n  = fmaxf(nx, EPSF);
    float th = tanhf(sc * n);
    float s  = th / (sc * n);
    float ny = fmaxf(s * nx, EPSF);
    float maxn = 0.999f / sc;
    if (ny > maxn) s *= maxn / ny;
    return s;
}

__device__ __forceinline__ float pdist(float G, float c, float sp, float np_, float nq) {
    float sc = sqrtf(c);
    float sq = expmap_scale(nq, c);
    float xy = sp * sq * G;
    float uy = -xy;
    float u2 = sp * sp * np_ * np_;
    float y2 = sq * sq * nq * nq;
    float A  = 1.f + 2.f * c * uy + c * y2;
    float B  = 1.f - c * u2;
    float num2 = A * A * u2 + 2.f * A * B * uy + B * B * y2;
    float den  = fmaxf(1.f + 2.f * c * uy + c * c * u2 * y2, EPSF);
    float nn   = sqrtf(fmaxf(num2, 0.f)) / den;
    float arg  = fminf(sc * nn, 1.f - EPSF);
    arg = fmaxf(arg, 0.f);
    return (2.f / sc) * atanhf(arg);
}

// ---------------- K1: fused protos (+transpose) and column partial sums ----------------
__global__ __launch_bounds__(256) void k_pre(const float* __restrict__ ds,
                                             const float* __restrict__ dq) {
    int b = blockIdx.x, t = threadIdx.x;
    if (b < 32) {
        int w = b;
        __shared__ float red[256];
        float acc = 0.f;
        for (int d = t; d < DIMN; d += 256) {
            float s = 0.f;
#pragma unroll
            for (int sh = 0; sh < 5; sh++) s += ds[(sh * WAYN + w) * DIMN + d];
            float p = s * 0.2f;
            g_protos[w * DIMN + d] = p;
            g_protosT[d * WAYN + w] = p;
            acc += p * p;
        }
        red[t] = acc;
        __syncthreads();
        for (int o = 128; o; o >>= 1) { if (t < o) red[t] += red[t + o]; __syncthreads(); }
        if (t == 0) g_pn[w] = sqrtf(red[0]);
    } else {
        int vb = b - 32;          // 0..79
        int cg = vb % 5, p = vb / 5;
        if (t < 128) {
            int c = cg * 128 + t;
            int r0 = p * 266, r1 = min(r0 + 266, 4256);
            float acc = 0.f;
            for (int r = r0; r < r1; r++)
                acc += (r < 160) ? ds[r * DIMN + c] : dq[(size_t)(r - 160) * DIMN + c];
            g_part[p * DIMN + c] = acc;
        }
    }
}

// ---------------- K2: controller MLP -> c[w], proto scale sp[w] ----------------
__global__ __launch_bounds__(256) void k_ctrl(const float* __restrict__ W1, const float* __restrict__ b1,
                                              const float* __restrict__ W2, const float* __restrict__ b2,
                                              const float* __restrict__ W3, const float* __restrict__ b3) {
    int w = blockIdx.x, t = threadIdx.x;
    __shared__ float ci[2 * DIMN];
    __shared__ float hpart[256];
    __shared__ float h1[128];
    __shared__ float h2[64];
    for (int d = t; d < DIMN; d += 256) {
        ci[d] = g_protos[w * DIMN + d];
        float s = 0.f;
#pragma unroll
        for (int p = 0; p < 16; p++) s += g_part[p * DIMN + d];
        ci[DIMN + d] = s * (1.0f / 4256.0f);
    }
    __syncthreads();
    {
        int o = t & 127, hf = t >> 7;
        const float* wp = W1 + (size_t)(hf * DIMN) * 128 + o;
        const float* cp = ci + hf * DIMN;
        float a0 = 0.f, a1 = 0.f, a2 = 0.f, a3 = 0.f;
#pragma unroll 4
        for (int d = 0; d < DIMN; d += 4) {
            a0 = fmaf(cp[d + 0], wp[(d + 0) * 128], a0);
            a1 = fmaf(cp[d + 1], wp[(d + 1) * 128], a1);
            a2 = fmaf(cp[d + 2], wp[(d + 2) * 128], a2);
            a3 = fmaf(cp[d + 3], wp[(d + 3) * 128], a3);
        }
        hpart[t] = (a0 + a1) + (a2 + a3);
    }
    __syncthreads();
    if (t < 128) h1[t] = fmaxf(hpart[t] + hpart[t + 128] + b1[t], 0.f);
    __syncthreads();
    if (t < 64) {
        float a = b2[t];
#pragma unroll 4
        for (int d = 0; d < 128; d++) a = fmaf(h1[d], W2[d * 64 + t], a);
        h2[t] = fmaxf(a, 0.f);
    }
    __syncthreads();
    if (t == 0) {
        float lg[5];
        for (int o = 0; o < 5; o++) {
            float a = b3[o];
            for (int d = 0; d < 64; d++) a = fmaf(h2[d], W3[d * 5 + o], a);
            lg[o] = a;
        }
        float m = lg[0];
        for (int o = 1; o < 5; o++) m = fmaxf(m, lg[o]);
        float se = 0.f, cv = 0.f;
        for (int o = 0; o < 5; o++) {
            float e = expf(lg[o] - m);
            se += e;
            cv += e * ((float)(o + 1) * 0.2f);
        }
        float c = cv / se;
        g_c[w]  = c;
        g_sp[w] = expmap_scale(g_pn[w], c);
    }
}

// ---------------- K3/K6: GEMM (32w x 32q tile) + distance epilogue ----------------
// A pre-transposed [640][32]; per k-step: 1 LDS.128 (A frag, broadcast) + 4 scalar
// LDS (B frag, broadcast) + 16 FMA. Double-buffered smem, 1 barrier per 64-k chunk.
#define STS_TILE(buf_)                                                            \
    do {                                                                          \
        *(float4*)&sm[(buf_) * 2048 + akr * 32 + aw4 * 4]        = ra0;           \
        *(float4*)&sm[(buf_) * 2048 + (akr + 32) * 32 + aw4 * 4] = ra1;           \
        int bb_ = 4096 + (buf_) * 2080;                                           \
        sm[bb_ + bqr * 65 + bk4 * 4 + 0] = rb0.x;                                 \
        sm[bb_ + bqr * 65 + bk4 * 4 + 1] = rb0.y;                                 \
        sm[bb_ + bqr * 65 + bk4 * 4 + 2] = rb0.z;                                 \
        sm[bb_ + bqr * 65 + bk4 * 4 + 3] = rb0.w;                                 \
        sm[bb_ + (bqr + 16) * 65 + bk4 * 4 + 0] = rb1.x;                          \
        sm[bb_ + (bqr + 16) * 65 + bk4 * 4 + 1] = rb1.y;                          \
        sm[bb_ + (bqr + 16) * 65 + bk4 * 4 + 2] = rb1.z;                          \
        sm[bb_ + (bqr + 16) * 65 + bk4 * 4 + 3] = rb1.w;                          \
    } while (0)

__global__ __launch_bounds__(256) void k_gemm_dist(const float* __restrict__ Bq,
                                                   float* __restrict__ outp, int pass) {
    const float* __restrict__ AT  = pass ? g_tmpT : g_protosT;
    const float* __restrict__ An  = pass ? g_tn   : g_pn;
    const float* __restrict__ Asc = pass ? g_st   : g_sp;

    __shared__ float sm[2 * 2048 + 2 * 2080];   // As dbl | Bs dbl ; Rs aliased later
    __shared__ float qns[32], scw[32], snw[32], ssw[32];

    int t = threadIdx.x;
    int q0 = blockIdx.x * 32;

    if (t < 32) { scw[t] = g_c[t]; snw[t] = An[t]; ssw[t] = Asc[t]; }

    int aw4 = t & 7, akr = t >> 3;      // A loader: k-row, w float4-group
    int bk4 = t & 15, bqr = t >> 4;     // B loader: q-row, k float4-group

    const float* aptr  = AT + akr * 32 + aw4 * 4;
    const float* bptr0 = Bq + (size_t)(q0 + bqr) * DIMN + bk4 * 4;
    const float* bptr1 = bptr0 + (size_t)16 * DIMN;

    float4 ra0, ra1, rb0, rb1;
    float q2a = 0.f, q2b = 0.f;

    ra0 = *(const float4*)(aptr);
    ra1 = *(const float4*)(aptr + 32 * 32);
    rb0 = *(const float4*)(bptr0);
    rb1 = *(const float4*)(bptr1);
    q2a += rb0.x * rb0.x + rb0.y * rb0.y + rb0.z * rb0.z + rb0.w * rb0.w;
    q2b += rb1.x * rb1.x + rb1.y * rb1.y + rb1.z * rb1.z + rb1.w * rb1.w;

    STS_TILE(0);
    __syncthreads();

    float acc[4][4];
#pragma unroll
    for (int i = 0; i < 4; i++)
#pragma unroll
        for (int j = 0; j < 4; j++) acc[i][j] = 0.f;

    int slice = t >> 6, ct = t & 63, wt = ct & 7, qt = ct >> 3;
    int kb = slice * 16;

    for (int c = 0; c < 10; c++) {
        int cur = c & 1;
        if (c < 9) {
            const float* ap = aptr + (c + 1) * 64 * 32;
            ra0 = *(const float4*)(ap);
            ra1 = *(const float4*)(ap + 32 * 32);
            rb0 = *(const float4*)(bptr0 + (c + 1) * 64);
            rb1 = *(const float4*)(bptr1 + (c + 1) * 64);
            q2a += rb0.x * rb0.x + rb0.y * rb0.y + rb0.z * rb0.z + rb0.w * rb0.w;
            q2b += rb1.x * rb1.x + rb1.y * rb1.y + rb1.z * rb1.z + rb1.w * rb1.w;
        }
        const float* Asb = sm + cur * 2048;
        const float* Bsb = sm + 4096 + cur * 2080;
#pragma unroll
        for (int kk = 0; kk < 16; kk++) {
            int k = kb + kk;
            float4 a = *(const float4*)&Asb[k * 32 + wt * 4];
            float b0 = Bsb[(qt * 4 + 0) * 65 + k];
            float b1 = Bsb[(qt * 4 + 1) * 65 + k];
            float b2 = Bsb[(qt * 4 + 2) * 65 + k];
            float b3 = Bsb[(qt * 4 + 3) * 65 + k];
            acc[0][0] = fmaf(a.x, b0, acc[0][0]); acc[0][1] = fmaf(a.x, b1, acc[0][1]);
            acc[0][2] = fmaf(a.x, b2, acc[0][2]); acc[0][3] = fmaf(a.x, b3, acc[0][3]);
            acc[1][0] = fmaf(a.y, b0, acc[1][0]); acc[1][1] = fmaf(a.y, b1, acc[1][1]);
            acc[1][2] = fmaf(a.y, b2, acc[1][2]); acc[1][3] = fmaf(a.y, b3, acc[1][3]);
            acc[2][0] = fmaf(a.z, b0, acc[2][0]); acc[2][1] = fmaf(a.z, b1, acc[2][1]);
            acc[2][2] = fmaf(a.z, b2, acc[2][2]); acc[2][3] = fmaf(a.z, b3, acc[2][3]);
            acc[3][0] = fmaf(a.w, b0, acc[3][0]); acc[3][1] = fmaf(a.w, b1, acc[3][1]);
            acc[3][2] = fmaf(a.w, b2, acc[3][2]); acc[3][3] = fmaf(a.w, b3, acc[3][3]);
        }
        if (c < 9) {
            STS_TILE((c + 1) & 1);
            __syncthreads();
        }
    }

    // query-norm reduce over the 16 loader lanes per q-row
#pragma unroll
    for (int off = 8; off >= 1; off >>= 1) {
        q2a += __shfl_down_sync(0xffffffffu, q2a, off);
        q2b += __shfl_down_sync(0xffffffffu, q2b, off);
    }
    if ((t & 15) == 0) { qns[bqr] = sqrtf(q2a); qns[bqr + 16] = sqrtf(q2b); }

    __syncthreads();          // tiles dead; alias Rs onto sm
    float* Rs = sm;
#pragma unroll
    for (int i = 0; i < 4; i++)
#pragma unroll
        for (int j = 0; j < 4; j++)
            Rs[slice * 1056 + (wt * 4 + i) * 33 + (qt * 4 + j)] = acc[i][j];
    __syncthreads();

#pragma unroll
    for (int r = 0; r < 4; r++) {
        int idx = r * 256 + t;
        int w, q;
        if (pass == 0) { w = idx >> 5; q = idx & 31; }
        else           { w = idx & 31; q = idx >> 5; }
        int o = w * 33 + q;
        float G = Rs[o] + Rs[1056 + o] + Rs[2112 + o] + Rs[3168 + o];
        float d = pdist(G, scw[w], ssw[w], snw[w], qns[q]);
        if (pass == 0) g_dis[w * QN + q0 + q] = d;
        else           outp[(size_t)(q0 + q) * WAYN + w] = -d * 0.0625f;
    }
}

// ---------------- K4: per-way top-10 (stable, ascending) + row sums ----------------
__global__ __launch_bounds__(512) void k_topk() {
    int w = blockIdx.x, t = threadIdx.x;
    __shared__ float sv[512 * RRN];
    __shared__ int   si[512 * RRN];
    __shared__ float red[512];

    float v[RRN]; int id[RRN];
#pragma unroll
    for (int i = 0; i < RRN; i++) { v[i] = __int_as_float(0x7f800000); id[i] = 0x7fffffff; }

    float sum = 0.f;
    const float* row = g_dis + w * QN;
    for (int i = 0; i < 8; i++) {
        int q = i * 512 + t;
        float x = row[q];
        sum += x;
        if (x < v[RRN - 1] || (x == v[RRN - 1] && q < id[RRN - 1])) {
            int p = RRN - 1;
            while (p > 0 && (x < v[p - 1] || (x == v[p - 1] && q < id[p - 1]))) {
                v[p] = v[p - 1]; id[p] = id[p - 1]; p--;
            }
            v[p] = x; id[p] = q;
        }
    }
    red[t] = sum;
#pragma unroll
    for (int i = 0; i < RRN; i++) { sv[t * RRN + i] = v[i]; si[t * RRN + i] = id[i]; }
    __syncthreads();

    for (int o = 256; o; o >>= 1) { if (t < o) red[t] += red[t + o]; __syncthreads(); }

    for (int off = 256; off >= 1; off >>= 1) {
        if (t < off) {
            float av[RRN], bv[RRN], mv[RRN];
            int   ai[RRN], bi[RRN], mi[RRN];
#pragma unroll
            for (int i = 0; i < RRN; i++) {
                av[i] = sv[t * RRN + i];          ai[i] = si[t * RRN + i];
                bv[i] = sv[(t + off) * RRN + i];  bi[i] = si[(t + off) * RRN + i];
            }
            int ia = 0, ib = 0;
#pragma unroll
            for (int i = 0; i < RRN; i++) {
                bool ta = (av[ia] < bv[ib]) || (av[ia] == bv[ib] && ai[ia] < bi[ib]);
                if (ta) { mv[i] = av[ia]; mi[i] = ai[ia]; ia++; }
                else    { mv[i] = bv[ib]; mi[i] = bi[ib]; ib++; }
            }
#pragma unroll
            for (int i = 0; i < RRN; i++) { sv[t * RRN + i] = mv[i]; si[t * RRN + i] = mi[i]; }
        }
        __syncthreads();
    }
    if (t < RRN) { g_nid[w * RRN + t] = sv[t]; g_nidx[w * RRN + t] = si[t]; }
    if (t == 0) {
        g_T[w] = red[0];
        float f = 0.f;
        for (int q = 0; q < RRN; q++) f += row[q];
        g_f10[w] = f;
    }
}

// ---------------- K5: fused stats + relation MLP + weighted query + test proto ----------------
__global__ __launch_bounds__(256) void k_small_wdq(const float* __restrict__ dq,
                                                   const float* __restrict__ Wr1, const float* __restrict__ br1,
                                                   const float* __restrict__ Wr2, const float* __restrict__ br2) {
    int i = blockIdx.x, t = threadIdx.x;
    __shared__ float sT[32], sf10[32];
    __shared__ float Dm[32][11];
    __shared__ float snid[10];
    __shared__ int   sidx[10];
    __shared__ float scn[32], snod[10];
    __shared__ float rin[22], hr[10], sor[11];
    __shared__ float siw[10];
    __shared__ float s_onw;
    __shared__ float red[256];

    if (t < 32) { sT[t] = g_T[t]; sf10[t] = g_f10[t]; }
    if (t < 10) { snid[t] = g_nid[i * RRN + t]; sidx[t] = g_nidx[i * RRN + t]; }
    __syncthreads();

    for (int u = t; u < 320; u += 256) {
        int j = u / 10, k = u % 10;
        Dm[j][k] = g_dis[j * QN + sidx[k]];
    }
    __syncthreads();

    if (t < 32) {
        float s = 0.f;
        for (int k = 0; k < 10; k++) s += Dm[t][k];
        scn[t] = s;
    } else if (t < 42) {
        int k = t - 32;
        float s = 0.f;
        for (int j = 0; j < 32; j++) s += Dm[j][k];
        snod[k] = (s - snid[k]) * (1.0f / 31.0f);
    }
    __syncthreads();

    if (t < 10) { rin[t] = snid[t]; rin[10 + t] = snod[t]; }
    if (t == 0) {
        float nsum = 0.f;
        for (int k = 0; k < 10; k++) nsum += snid[k];
        rin[20] = (sT[i] - nsum) * (1.0f / (float)(QN - RRN));
        float sa = 0.f;
        for (int j = 0; j < i; j++) sa += sT[j] - scn[j];
        float sb = 0.f;
        for (int j = i + 1; j < 32; j++) sb += sT[j] - sf10[j];
        rin[21] = (sa + sb) * (1.0f / (float)((WAYN - 1) * (QN - RRN)));
    }
    __syncthreads();

    if (t < 10) {
        float a = br1[t];
        for (int d = 0; d < 22; d++) a = fmaf(rin[d], Wr1[d * 10 + t], a);
        hr[t] = fmaxf(a, 0.f);
    }
    __syncthreads();
    if (t < 11) {
        float a = br2[t];
        for (int r = 0; r < 10; r++) a = fmaf(hr[r], Wr2[r * 11 + t], a);
        sor[t] = a;
    }
    __syncthreads();
    if (t == 0) {
        float m = sor[0];
        for (int k = 1; k < 10; k++) m = fmaxf(m, sor[k]);
        float e[10], se = 0.f;
        for (int k = 0; k < 10; k++) { e[k] = expf(sor[k] - m); se += e[k]; }
        for (int k = 0; k < 10; k++) siw[k] = e[k] / se;
        s_onw = 1.f / (1.f + expf(-sor[10]));
    }
    __syncthreads();

    // weighted query + test proto (transposed store) + its norm/scale
    float nrm = 0.f;
    if (t < 160) {
        float onw = s_onw, om = 1.f - onw;
        float4 wd = make_float4(0.f, 0.f, 0.f, 0.f);
#pragma unroll
        for (int k = 0; k < 10; k++) {
            float4 qv = *((const float4*)(dq + (size_t)sidx[k] * DIMN) + t);
            float wk = siw[k];
            wd.x = fmaf(wk, qv.x, wd.x); wd.y = fmaf(wk, qv.y, wd.y);
            wd.z = fmaf(wk, qv.z, wd.z); wd.w = fmaf(wk, qv.w, wd.w);
        }
        float4 pv = *((const float4*)(g_protos + i * DIMN) + t);
        float4 tm;
        tm.x = pv.x * onw + wd.x * om;
        tm.y = pv.y * onw + wd.y * om;
        tm.z = pv.z * onw + wd.z * om;
        tm.w = pv.w * onw + wd.w * om;
        int d0 = t * 4;
        g_tmpT[(d0 + 0) * WAYN + i] = tm.x;
        g_tmpT[(d0 + 1) * WAYN + i] = tm.y;
        g_tmpT[(d0 + 2) * WAYN + i] = tm.z;
        g_tmpT[(d0 + 3) * WAYN + i] = tm.w;
        nrm = tm.x * tm.x + tm.y * tm.y + tm.z * tm.z + tm.w * tm.w;
    }
    red[t] = nrm;
    __syncthreads();
    for (int o = 128; o; o >>= 1) { if (t < o) red[t] += red[t + o]; __syncthreads(); }
    if (t == 0) {
        float nt = sqrtf(red[0]);
        g_tn[i] = nt;
        g_st[i] = expmap_scale(nt, g_c[i]);
    }
}

// ---------------- launch ----------------
extern "C" void kernel_launch(void* const* d_in, const int* in_sizes, int n_in,
                              void* d_out, int out_size) {
    const float* ds  = (const float*)d_in[0];
    const float* dq  = (const float*)d_in[1];
    const float* W1  = (const float*)d_in[2];
    const float* b1  = (const float*)d_in[3];
    const float* W2  = (const float*)d_in[4];
    const float* b2  = (const float*)d_in[5];
    const float* W3  = (const float*)d_in[6];
    const float* b3  = (const float*)d_in[7];
    const float* Wr1 = (const float*)d_in[8];
    const float* br1 = (const float*)d_in[9];
    const float* Wr2 = (const float*)d_in[10];
    const float* br2 = (const float*)d_in[11];
    float* out = (float*)d_out;

    k_pre<<<112, 256>>>(ds, dq);
    k_ctrl<<<32, 256>>>(W1, b1, W2, b2, W3, b3);
    k_gemm_dist<<<128, 256>>>(dq, out, 0);
    k_topk<<<32, 512>>>();
    k_small_wdq<<<32, 256>>>(dq, Wr1, br1, Wr2, br2);
    k_gemm_dist<<<128, 256>>>(dq, out, 1);
}

// round 6
// speedup vs baseline: 1.4244x; 1.4244x over previous
#include <cuda_runtime.h>

#define EPSF 1e-5f

static constexpr int WAYN = 32;
static constexpr int QN   = 4096;
static constexpr int DIMN = 640;
static constexpr int RRN  = 10;

// ---------------- scratch (device globals; no allocation) ----------------
__device__ float g_protos[WAYN * DIMN];
__device__ float g_pn[WAYN];
__device__ float g_part[16 * DIMN];
__device__ float g_c[WAYN];
__device__ float g_sp[WAYN];
__device__ float g_dis[WAYN * QN];
__device__ float g_T[WAYN];
__device__ float g_f10[WAYN];
__device__ float g_nid[WAYN * RRN];
__device__ int   g_nidx[WAYN * RRN];
__device__ float g_iw[WAYN * RRN];
__device__ float g_onw[WAYN];
__device__ float g_tmp[WAYN * DIMN];
__device__ float g_tn[WAYN];
__device__ float g_st[WAYN];

// ---------------- math helpers ----------------
__device__ __forceinline__ float expmap_scale(float nx, float c) {
    float sc = sqrtf(c);
    float n  = fmaxf(nx, EPSF);
    float th = tanhf(sc * n);
    float s  = th / (sc * n);
    float ny = fmaxf(s * nx, EPSF);
    float maxn = 0.999f / sc;
    if (ny > maxn) s *= maxn / ny;
    return s;
}

__device__ __forceinline__ float pdist(float G, float c, float sp, float np_, float nq) {
    float sc = sqrtf(c);
    float sq = expmap_scale(nq, c);
    float xy = sp * sq * G;
    float uy = -xy;
    float u2 = sp * sp * np_ * np_;
    float y2 = sq * sq * nq * nq;
    float A  = 1.f + 2.f * c * uy + c * y2;
    float B  = 1.f - c * u2;
    float num2 = A * A * u2 + 2.f * A * B * uy + B * B * y2;
    float den  = fmaxf(1.f + 2.f * c * uy + c * c * u2 * y2, EPSF);
    float nn   = sqrtf(fmaxf(num2, 0.f)) / den;
    float arg  = fminf(sc * nn, 1.f - EPSF);
    arg = fmaxf(arg, 0.f);
    return (2.f / sc) * atanhf(arg);
}

// ---------------- K1: protos + proto norms ----------------
__global__ void k_protos(const float* __restrict__ ds) {
    int w = blockIdx.x, t = threadIdx.x;
    __shared__ float red[256];
    float acc = 0.f;
    for (int d = t; d < DIMN; d += 256) {
        float s = 0.f;
#pragma unroll
        for (int sh = 0; sh < 5; sh++) s += ds[(sh * WAYN + w) * DIMN + d];
        float p = s * 0.2f;
        g_protos[w * DIMN + d] = p;
        acc += p * p;
    }
    red[t] = acc;
    __syncthreads();
    for (int o = 128; o; o >>= 1) { if (t < o) red[t] += red[t + o]; __syncthreads(); }
    if (t == 0) g_pn[w] = sqrtf(red[0]);
}

// ---------------- K2: deterministic column partial-sums for all_data ----------------
__global__ void k_colsum(const float* __restrict__ ds, const float* __restrict__ dq) {
    int c = blockIdx.x * 128 + threadIdx.x;
    int p = blockIdx.y;
    int r0 = p * 266, r1 = min(r0 + 266, 4256);
    float acc = 0.f;
    for (int r = r0; r < r1; r++)
        acc += (r < 160) ? ds[r * DIMN + c] : dq[(size_t)(r - 160) * DIMN + c];
    g_part[p * DIMN + c] = acc;
}

// ---------------- K3: controller MLP -> c[w], proto scale sp[w] ----------------
__global__ void k_ctrl(const float* __restrict__ W1, const float* __restrict__ b1,
                       const float* __restrict__ W2, const float* __restrict__ b2,
                       const float* __restrict__ W3, const float* __restrict__ b3) {
    int w = blockIdx.x, t = threadIdx.x;
    __shared__ float ci[2 * DIMN];
    __shared__ float h1[128];
    __shared__ float h2[64];
    for (int d = t; d < DIMN; d += 128) {
        ci[d] = g_protos[w * DIMN + d];
        float s = 0.f;
#pragma unroll
        for (int p = 0; p < 16; p++) s += g_part[p * DIMN + d];
        ci[DIMN + d] = s * (1.0f / 4256.0f);
    }
    __syncthreads();
    {
        float a = b1[t];
        for (int d = 0; d < 2 * DIMN; d++) a = fmaf(ci[d], W1[d * 128 + t], a);
        h1[t] = fmaxf(a, 0.f);
    }
    __syncthreads();
    if (t < 64) {
        float a = b2[t];
        for (int d = 0; d < 128; d++) a = fmaf(h1[d], W2[d * 64 + t], a);
        h2[t] = fmaxf(a, 0.f);
    }
    __syncthreads();
    if (t == 0) {
        float lg[5];
        for (int o = 0; o < 5; o++) {
            float a = b3[o];
            for (int d = 0; d < 64; d++) a = fmaf(h2[d], W3[d * 5 + o], a);
            lg[o] = a;
        }
        float m = lg[0];
        for (int o = 1; o < 5; o++) m = fmaxf(m, lg[o]);
        float se = 0.f, cv = 0.f;
        for (int o = 0; o < 5; o++) {
            float e = expf(lg[o] - m);
            se += e;
            cv += e * ((float)(o + 1) * 0.2f);
        }
        float c = cv / se;
        g_c[w]  = c;
        g_sp[w] = expmap_scale(g_pn[w], c);
    }
}

// ---------------- K4/K8: GEMM (32 x 32q tile) + distance epilogue ----------------
__global__ __launch_bounds__(256) void k_gemm_dist(const float* __restrict__ Bq,
                                                   float* __restrict__ outp, int pass) {
    const float* __restrict__ Amat = pass ? g_tmp : g_protos;
    const float* __restrict__ An   = pass ? g_tn  : g_pn;
    const float* __restrict__ Asc  = pass ? g_st  : g_sp;

    __shared__ float As[32][33];
    __shared__ float Bs[32][33];
    __shared__ float Rs[4][1024];
    __shared__ float qns[32];

    int t = threadIdx.x;
    int q0 = blockIdx.x * 32;
    int slice = t >> 6;
    int ct = t & 63;
    int wt = ct & 7;
    int qt = ct >> 3;
    int lw = t >> 3;
    int lk = (t & 7) * 4;

    float acc[4][4];
#pragma unroll
    for (int i = 0; i < 4; i++)
#pragma unroll
        for (int j = 0; j < 4; j++) acc[i][j] = 0.f;

    float q2acc = 0.f;
    const float* arow = Amat + lw * DIMN + lk;
    const float* brow = Bq + (size_t)(q0 + lw) * DIMN + lk;

    for (int k0 = 0; k0 < DIMN; k0 += 32) {
        float4 av = *(const float4*)(arow + k0);
        float4 bv = *(const float4*)(brow + k0);
        As[lw][lk + 0] = av.x; As[lw][lk + 1] = av.y; As[lw][lk + 2] = av.z; As[lw][lk + 3] = av.w;
        Bs[lw][lk + 0] = bv.x; Bs[lw][lk + 1] = bv.y; Bs[lw][lk + 2] = bv.z; Bs[lw][lk + 3] = bv.w;
        q2acc += bv.x * bv.x + bv.y * bv.y + bv.z * bv.z + bv.w * bv.w;
        __syncthreads();
        int kb = slice * 8;
#pragma unroll
        for (int kk = 0; kk < 8; kk++) {
            int k = kb + kk;
            float a[4], b[4];
#pragma unroll
            for (int i = 0; i < 4; i++) a[i] = As[wt * 4 + i][k];
#pragma unroll
            for (int j = 0; j < 4; j++) b[j] = Bs[qt * 4 + j][k];
#pragma unroll
            for (int i = 0; i < 4; i++)
#pragma unroll
                for (int j = 0; j < 4; j++) acc[i][j] = fmaf(a[i], b[j], acc[i][j]);
        }
        __syncthreads();
    }

    q2acc += __shfl_xor_sync(0xffffffffu, q2acc, 1);
    q2acc += __shfl_xor_sync(0xffffffffu, q2acc, 2);
    q2acc += __shfl_xor_sync(0xffffffffu, q2acc, 4);
    if ((t & 7) == 0) qns[lw] = sqrtf(q2acc);

#pragma unroll
    for (int i = 0; i < 4; i++)
#pragma unroll
        for (int j = 0; j < 4; j++)
            Rs[slice][(wt * 4 + i) * 32 + qt * 4 + j] = acc[i][j];
    __syncthreads();

#pragma unroll
    for (int r = 0; r < 4; r++) {
        int o = t + 256 * r;
        int w = o >> 5, q = o & 31;
        float G = Rs[0][o] + Rs[1][o] + Rs[2][o] + Rs[3][o];
        float d = pdist(G, g_c[w], Asc[w], An[w], qns[q]);
        if (pass == 0) g_dis[w * QN + q0 + q] = d;
        else           outp[(size_t)(q0 + q) * WAYN + w] = -d * (1.0f / 16.0f);
    }
}

// ---------------- K5: per-way top-10 via register-resident 64-bit keys ----------------
// key = (float_bits << 32) | index  (distances >= 0, so uint order == float order;
// index uniquely breaks ties -> exact stable argsort semantics).
// 512 threads x 8 keys each, static-index bubble sort in registers, then 10
// pop-the-global-min rounds with warp shuffle reductions. No local memory.
__global__ __launch_bounds__(512) void k_topk() {
    int w = blockIdx.x, t = threadIdx.x;
    int lane = t & 31, wid = t >> 5;
    const float* row = g_dis + w * QN;

    __shared__ float sred[16];
    __shared__ unsigned long long swin[16];
    __shared__ unsigned long long winner;

    unsigned long long k[8];
    float sum = 0.f;
#pragma unroll
    for (int i = 0; i < 8; i++) {
        int q = i * 512 + t;
        float x = row[q];
        sum += x;
        k[i] = ((unsigned long long)__float_as_uint(x) << 32) | (unsigned)q;
    }

    // static bubble network: ascending sort of 8 keys, pure registers
#pragma unroll
    for (int i = 0; i < 8; i++)
#pragma unroll
        for (int j = 0; j < 7; j++) {
            if (j < 7 - i) {
                unsigned long long lo = (k[j] < k[j + 1]) ? k[j] : k[j + 1];
                unsigned long long hi = (k[j] < k[j + 1]) ? k[j + 1] : k[j];
                k[j] = lo; k[j + 1] = hi;
            }
        }

    // row sum reduction
#pragma unroll
    for (int off = 16; off; off >>= 1) sum += __shfl_down_sync(0xffffffffu, sum, off);
    if (lane == 0) sred[wid] = sum;
    __syncthreads();
    if (t == 0) {
        float s = 0.f;
        for (int i = 0; i < 16; i++) s += sred[i];
        g_T[w] = s;
        float f = 0.f;
        for (int q = 0; q < RRN; q++) f += row[q];
        g_f10[w] = f;
    }

    // 10 rounds of global pop-min
    for (int r = 0; r < RRN; r++) {
        unsigned long long m = k[0];
#pragma unroll
        for (int off = 16; off; off >>= 1) {
            unsigned long long o = __shfl_down_sync(0xffffffffu, m, off);
            if (o < m) m = o;
        }
        if (lane == 0) swin[wid] = m;
        __syncthreads();
        if (t < 16) {
            unsigned long long mm = swin[t];
#pragma unroll
            for (int off = 8; off; off >>= 1) {
                unsigned long long o = __shfl_down_sync(0x0000ffffu, mm, off);
                if (o < mm) mm = o;
            }
            if (t == 0) {
                winner = mm;
                g_nid[w * RRN + r]  = __uint_as_float((unsigned)(mm >> 32));
                g_nidx[w * RRN + r] = (int)(mm & 0xffffffffu);
            }
        }
        __syncthreads();
        if (k[0] == winner) {      // unique holder advances (static shifts)
#pragma unroll
            for (int i = 0; i < 7; i++) k[i] = k[i + 1];
            k[7] = 0xFFFFFFFFFFFFFFFFULL;
        }
    }
}

// ---------------- K6: stats + relation MLP -> i_w, onw ----------------
__global__ __launch_bounds__(1024) void k_small(const float* __restrict__ Wr1, const float* __restrict__ br1,
                                                const float* __restrict__ Wr2, const float* __restrict__ br2) {
    __shared__ float sT[32], sf10[32];
    __shared__ float snid[32][10];
    __shared__ int   sidx[32][10];
    __shared__ float scn[32][32];
    __shared__ float snod[32][10];
    int t = threadIdx.x;

    if (t < 32) { sT[t] = g_T[t]; sf10[t] = g_f10[t]; }
    if (t < 320) { int i = t / 10, kk = t % 10; snid[i][kk] = g_nid[t]; sidx[i][kk] = g_nidx[t]; }
    __syncthreads();

    {
        int i = t >> 5, j = t & 31;
        float s = 0.f;
        for (int kk = 0; kk < 10; kk++) s += g_dis[j * QN + sidx[i][kk]];
        scn[i][j] = s;
    }
    if (t < 320) {
        int i = t / 10, kk = t % 10;
        int q = sidx[i][kk];
        float s = 0.f;
        for (int j = 0; j < 32; j++) s += g_dis[j * QN + q];
        snod[i][kk] = (s - snid[i][kk]) * (1.0f / 31.0f);
    }
    __syncthreads();

    if (t < 32) {
        int i = t;
        float nsum = 0.f;
        for (int kk = 0; kk < 10; kk++) nsum += snid[i][kk];
        float oid = (sT[i] - nsum) * (1.0f / (float)(QN - RRN));
        float sa = 0.f;
        for (int j = 0; j < i; j++) sa += sT[j] - scn[i][j];
        float sb = 0.f;
        for (int j = i + 1; j < 32; j++) sb += sT[j] - sf10[j];
        float ood = (sa + sb) * (1.0f / (float)((WAYN - 1) * (QN - RRN)));

        float rin[22];
        for (int kk = 0; kk < 10; kk++) { rin[kk] = snid[i][kk]; rin[10 + kk] = snod[i][kk]; }
        rin[20] = oid; rin[21] = ood;

        float hr[10];
        for (int r = 0; r < 10; r++) {
            float a = br1[r];
            for (int d = 0; d < 22; d++) a = fmaf(rin[d], Wr1[d * 10 + r], a);
            hr[r] = fmaxf(a, 0.f);
        }
        float orr[11];
        for (int j = 0; j < 11; j++) {
            float a = br2[j];
            for (int r = 0; r < 10; r++) a = fmaf(hr[r], Wr2[r * 11 + j], a);
            orr[j] = a;
        }
        float m = orr[0];
        for (int kk = 1; kk < 10; kk++) m = fmaxf(m, orr[kk]);
        float e[10], se = 0.f;
        for (int kk = 0; kk < 10; kk++) { e[kk] = expf(orr[kk] - m); se += e[kk]; }
        for (int kk = 0; kk < 10; kk++) g_iw[i * 10 + kk] = e[kk] / se;
        g_onw[i] = 1.f / (1.f + expf(-orr[10]));
    }
}

// ---------------- K7: weighted query + test proto (raw) + its norm/scale ----------------
__global__ void k_wdq(const float* __restrict__ dq) {
    int w = blockIdx.x, t = threadIdx.x;
    __shared__ float iw[10];
    __shared__ int   id[10];
    __shared__ float red[256];
    if (t < 10) { iw[t] = g_iw[w * 10 + t]; id[t] = g_nidx[w * 10 + t]; }
    __syncthreads();
    float onw = g_onw[w];
    float om  = 1.f - onw;
    float4 wd = make_float4(0.f, 0.f, 0.f, 0.f);
#pragma unroll
    for (int kk = 0; kk < 10; kk++) {
        float4 qv = *((const float4*)(dq + (size_t)id[kk] * DIMN) + t);
        float wk = iw[kk];
        wd.x = fmaf(wk, qv.x, wd.x); wd.y = fmaf(wk, qv.y, wd.y);
        wd.z = fmaf(wk, qv.z, wd.z); wd.w = fmaf(wk, qv.w, wd.w);
    }
    float4 pv = *((const float4*)(g_protos + w * DIMN) + t);
    float4 tm;
    tm.x = pv.x * onw + wd.x * om;
    tm.y = pv.y * onw + wd.y * om;
    tm.z = pv.z * onw + wd.z * om;
    tm.w = pv.w * onw + wd.w * om;
    *((float4*)(g_tmp + w * DIMN) + t) = tm;

    red[t] = tm.x * tm.x + tm.y * tm.y + tm.z * tm.z + tm.w * tm.w;
    if (t < 96) red[160 + t] = 0.f;
    __syncthreads();
    for (int o = 128; o; o >>= 1) { if (t < o) red[t] += red[t + o]; __syncthreads(); }
    if (t == 0) {
        float nt = sqrtf(red[0]);
        g_tn[w] = nt;
        g_st[w] = expmap_scale(nt, g_c[w]);
    }
}

// ---------------- launch ----------------
extern "C" void kernel_launch(void* const* d_in, const int* in_sizes, int n_in,
                              void* d_out, int out_size) {
    const float* ds  = (const float*)d_in[0];
    const float* dq  = (const float*)d_in[1];
    const float* W1  = (const float*)d_in[2];
    const float* b1  = (const float*)d_in[3];
    const float* W2  = (const float*)d_in[4];
    const float* b2  = (const float*)d_in[5];
    const float* W3  = (const float*)d_in[6];
    const float* b3  = (const float*)d_in[7];
    const float* Wr1 = (const float*)d_in[8];
    const float* br1 = (const float*)d_in[9];
    const float* Wr2 = (const float*)d_in[10];
    const float* br2 = (const float*)d_in[11];
    float* out = (float*)d_out;

    k_protos<<<32, 256>>>(ds);
    k_colsum<<<dim3(5, 16), 128>>>(ds, dq);
    k_ctrl<<<32, 128>>>(W1, b1, W2, b2, W3, b3);
    k_gemm_dist<<<128, 256>>>(dq, out, 0);
    k_topk<<<32, 512>>>();
    k_small<<<1, 1024>>>(Wr1, br1, Wr2, br2);
    k_wdq<<<32, 160>>>(dq);
    k_gemm_dist<<<128, 256>>>(dq, out, 1);
}

// round 9
// speedup vs baseline: 1.5432x; 1.0834x over previous
#include <cuda_runtime.h>

#define EPSF 1e-5f

static constexpr int WAYN = 32;
static constexpr int QN   = 4096;
static constexpr int DIMN = 640;
static constexpr int RRN  = 10;

// ---------------- scratch (device globals; no allocation) ----------------
__device__ float g_protos[WAYN * DIMN];
__device__ float g_protosT[DIMN * WAYN];   // [k][w]
__device__ float g_pn[WAYN];
__device__ float g_part[16 * DIMN];
__device__ float g_c[WAYN];
__device__ float g_sp[WAYN];
__device__ float g_dis[WAYN * QN];
__device__ float g_T[WAYN];
__device__ float g_f10[WAYN];
__device__ float g_nid[WAYN * RRN];
__device__ int   g_nidx[WAYN * RRN];
__device__ float g_iw[WAYN * RRN];
__device__ float g_onw[WAYN];
__device__ float g_tmpT[DIMN * WAYN];      // [k][w]
__device__ float g_tn[WAYN];
__device__ float g_st[WAYN];

// ---------------- math helpers ----------------
__device__ __forceinline__ float expmap_scale(float nx, float c) {
    float sc = sqrtf(c);
    float n  = fmaxf(nx, EPSF);
    float th = tanhf(sc * n);
    float s  = th / (sc * n);
    float ny = fmaxf(s * nx, EPSF);
    float maxn = 0.999f / sc;
    if (ny > maxn) s *= maxn / ny;
    return s;
}

__device__ __forceinline__ float pdist(float G, float c, float sp, float np_, float nq) {
    float sc = sqrtf(c);
    float sq = expmap_scale(nq, c);
    float xy = sp * sq * G;
    float uy = -xy;
    float u2 = sp * sp * np_ * np_;
    float y2 = sq * sq * nq * nq;
    float A  = 1.f + 2.f * c * uy + c * y2;
    float B  = 1.f - c * u2;
    float num2 = A * A * u2 + 2.f * A * B * uy + B * B * y2;
    float den  = fmaxf(1.f + 2.f * c * uy + c * c * u2 * y2, EPSF);
    float nn   = sqrtf(fmaxf(num2, 0.f)) / den;
    float arg  = fminf(sc * nn, 1.f - EPSF);
    arg = fmaxf(arg, 0.f);
    return (2.f / sc) * atanhf(arg);
}

// ---------------- K1: protos + transpose + proto norms ----------------
__global__ void k_protos(const float* __restrict__ ds) {
    int w = blockIdx.x, t = threadIdx.x;
    __shared__ float red[256];
    float acc = 0.f;
    for (int d = t; d < DIMN; d += 256) {
        float s = 0.f;
#pragma unroll
        for (int sh = 0; sh < 5; sh++) s += ds[(sh * WAYN + w) * DIMN + d];
        float p = s * 0.2f;
        g_protos[w * DIMN + d] = p;
        g_protosT[d * WAYN + w] = p;
        acc += p * p;
    }
    red[t] = acc;
    __syncthreads();
    for (int o = 128; o; o >>= 1) { if (t < o) red[t] += red[t + o]; __syncthreads(); }
    if (t == 0) g_pn[w] = sqrtf(red[0]);
}

// ---------------- K2: deterministic column partial-sums for all_data ----------------
__global__ void k_colsum(const float* __restrict__ ds, const float* __restrict__ dq) {
    int c = blockIdx.x * 128 + threadIdx.x;
    int p = blockIdx.y;
    int r0 = p * 266, r1 = min(r0 + 266, 4256);
    float acc = 0.f;
    for (int r = r0; r < r1; r++)
        acc += (r < 160) ? ds[r * DIMN + c] : dq[(size_t)(r - 160) * DIMN + c];
    g_part[p * DIMN + c] = acc;
}

// ---------------- K3: controller MLP -> c[w], proto scale sp[w] ----------------
__global__ void k_ctrl(const float* __restrict__ W1, const float* __restrict__ b1,
                       const float* __restrict__ W2, const float* __restrict__ b2,
                       const float* __restrict__ W3, const float* __restrict__ b3) {
    int w = blockIdx.x, t = threadIdx.x;
    __shared__ float ci[2 * DIMN];
    __shared__ float h1[128];
    __shared__ float h2[64];
    for (int d = t; d < DIMN; d += 128) {
        ci[d] = g_protos[w * DIMN + d];
        float s = 0.f;
#pragma unroll
        for (int p = 0; p < 16; p++) s += g_part[p * DIMN + d];
        ci[DIMN + d] = s * (1.0f / 4256.0f);
    }
    __syncthreads();
    {
        float a = b1[t];
        for (int d = 0; d < 2 * DIMN; d++) a = fmaf(ci[d], W1[d * 128 + t], a);
        h1[t] = fmaxf(a, 0.f);
    }
    __syncthreads();
    if (t < 64) {
        float a = b2[t];
        for (int d = 0; d < 128; d++) a = fmaf(h1[d], W2[d * 64 + t], a);
        h2[t] = fmaxf(a, 0.f);
    }
    __syncthreads();
    if (t == 0) {
        float lg[5];
        for (int o = 0; o < 5; o++) {
            float a = b3[o];
            for (int d = 0; d < 64; d++) a = fmaf(h2[d], W3[d * 5 + o], a);
            lg[o] = a;
        }
        float m = lg[0];
        for (int o = 1; o < 5; o++) m = fmaxf(m, lg[o]);
        float se = 0.f, cv = 0.f;
        for (int o = 0; o < 5; o++) {
            float e = expf(lg[o] - m);
            se += e;
            cv += e * ((float)(o + 1) * 0.2f);
        }
        float c = cv / se;
        g_c[w]  = c;
        g_sp[w] = expmap_scale(g_pn[w], c);
    }
}

// ---------------- K4/K8: GEMM (32w x 32q tile) + distance epilogue ----------------
// A pre-transposed [640][32]; per k-step: 1 LDS.128 (A frag, broadcast) + 4 scalar
// LDS (B frag, broadcast) + 16 FMA. Double-buffered smem, 1 barrier per 64-k chunk.
#define STS_TILE(buf_)                                                            \
    do {                                                                          \
        *(float4*)&sm[(buf_) * 2048 + akr * 32 + aw4 * 4]        = ra0;           \
        *(float4*)&sm[(buf_) * 2048 + (akr + 32) * 32 + aw4 * 4] = ra1;           \
        int bb_ = 4096 + (buf_) * 2080;                                           \
        sm[bb_ + bqr * 65 + bk4 * 4 + 0] = rb0.x;                                 \
        sm[bb_ + bqr * 65 + bk4 * 4 + 1] = rb0.y;                                 \
        sm[bb_ + bqr * 65 + bk4 * 4 + 2] = rb0.z;                                 \
        sm[bb_ + bqr * 65 + bk4 * 4 + 3] = rb0.w;                                 \
        sm[bb_ + (bqr + 16) * 65 + bk4 * 4 + 0] = rb1.x;                          \
        sm[bb_ + (bqr + 16) * 65 + bk4 * 4 + 1] = rb1.y;                          \
        sm[bb_ + (bqr + 16) * 65 + bk4 * 4 + 2] = rb1.z;                          \
        sm[bb_ + (bqr + 16) * 65 + bk4 * 4 + 3] = rb1.w;                          \
    } while (0)

__global__ __launch_bounds__(256) void k_gemm_dist(const float* __restrict__ Bq,
                                                   float* __restrict__ outp, int pass) {
    const float* __restrict__ AT  = pass ? g_tmpT : g_protosT;
    const float* __restrict__ An  = pass ? g_tn   : g_pn;
    const float* __restrict__ Asc = pass ? g_st   : g_sp;

    __shared__ float sm[2 * 2048 + 2 * 2080];
    __shared__ float qns[32], scw[32], snw[32], ssw[32];

    int t = threadIdx.x;
    int q0 = blockIdx.x * 32;

    if (t < 32) { scw[t] = g_c[t]; snw[t] = An[t]; ssw[t] = Asc[t]; }

    int aw4 = t & 7, akr = t >> 3;
    int bk4 = t & 15, bqr = t >> 4;

    const float* aptr  = AT + akr * 32 + aw4 * 4;
    const float* bptr0 = Bq + (size_t)(q0 + bqr) * DIMN + bk4 * 4;
    const float* bptr1 = bptr0 + (size_t)16 * DIMN;

    float4 ra0, ra1, rb0, rb1;
    float q2a = 0.f, q2b = 0.f;

    ra0 = *(const float4*)(aptr);
    ra1 = *(const float4*)(aptr + 32 * 32);
    rb0 = *(const float4*)(bptr0);
    rb1 = *(const float4*)(bptr1);
    q2a += rb0.x * rb0.x + rb0.y * rb0.y + rb0.z * rb0.z + rb0.w * rb0.w;
    q2b += rb1.x * rb1.x + rb1.y * rb1.y + rb1.z * rb1.z + rb1.w * rb1.w;

    STS_TILE(0);
    __syncthreads();

    float acc[4][4];
#pragma unroll
    for (int i = 0; i < 4; i++)
#pragma unroll
        for (int j = 0; j < 4; j++) acc[i][j] = 0.f;

    int slice = t >> 6, ct = t & 63, wt = ct & 7, qt = ct >> 3;
    int kb = slice * 16;

    for (int c = 0; c < 10; c++) {
        int cur = c & 1;
        if (c < 9) {
            const float* ap = aptr + (c + 1) * 64 * 32;
            ra0 = *(const float4*)(ap);
            ra1 = *(const float4*)(ap + 32 * 32);
            rb0 = *(const float4*)(bptr0 + (c + 1) * 64);
            rb1 = *(const float4*)(bptr1 + (c + 1) * 64);
            q2a += rb0.x * rb0.x + rb0.y * rb0.y + rb0.z * rb0.z + rb0.w * rb0.w;
            q2b += rb1.x * rb1.x + rb1.y * rb1.y + rb1.z * rb1.z + rb1.w * rb1.w;
        }
        const float* Asb = sm + cur * 2048;
        const float* Bsb = sm + 4096 + cur * 2080;
#pragma unroll
        for (int kk = 0; kk < 16; kk++) {
            int k = kb + kk;
            float4 a = *(const float4*)&Asb[k * 32 + wt * 4];
            float b0 = Bsb[(qt * 4 + 0) * 65 + k];
            float b1 = Bsb[(qt * 4 + 1) * 65 + k];
            float b2 = Bsb[(qt * 4 + 2) * 65 + k];
            float b3 = Bsb[(qt * 4 + 3) * 65 + k];
            acc[0][0] = fmaf(a.x, b0, acc[0][0]); acc[0][1] = fmaf(a.x, b1, acc[0][1]);
            acc[0][2] = fmaf(a.x, b2, acc[0][2]); acc[0][3] = fmaf(a.x, b3, acc[0][3]);
            acc[1][0] = fmaf(a.y, b0, acc[1][0]); acc[1][1] = fmaf(a.y, b1, acc[1][1]);
            acc[1][2] = fmaf(a.y, b2, acc[1][2]); acc[1][3] = fmaf(a.y, b3, acc[1][3]);
            acc[2][0] = fmaf(a.z, b0, acc[2][0]); acc[2][1] = fmaf(a.z, b1, acc[2][1]);
            acc[2][2] = fmaf(a.z, b2, acc[2][2]); acc[2][3] = fmaf(a.z, b3, acc[2][3]);
            acc[3][0] = fmaf(a.w, b0, acc[3][0]); acc[3][1] = fmaf(a.w, b1, acc[3][1]);
            acc[3][2] = fmaf(a.w, b2, acc[3][2]); acc[3][3] = fmaf(a.w, b3, acc[3][3]);
        }
        if (c < 9) {
            STS_TILE((c + 1) & 1);
            __syncthreads();
        }
    }

#pragma unroll
    for (int off = 8; off >= 1; off >>= 1) {
        q2a += __shfl_down_sync(0xffffffffu, q2a, off);
        q2b += __shfl_down_sync(0xffffffffu, q2b, off);
    }
    if ((t & 15) == 0) { qns[bqr] = sqrtf(q2a); qns[bqr + 16] = sqrtf(q2b); }

    __syncthreads();
    float* Rs = sm;
#pragma unroll
    for (int i = 0; i < 4; i++)
#pragma unroll
        for (int j = 0; j < 4; j++)
            Rs[slice * 1056 + (wt * 4 + i) * 33 + (qt * 4 + j)] = acc[i][j];
    __syncthreads();

#pragma unroll
    for (int r = 0; r < 4; r++) {
        int idx = r * 256 + t;
        int w, q;
        if (pass == 0) { w = idx >> 5; q = idx & 31; }
        else           { w = idx & 31; q = idx >> 5; }
        int o = w * 33 + q;
        float G = Rs[o] + Rs[1056 + o] + Rs[2112 + o] + Rs[3168 + o];
        float d = pdist(G, scw[w], ssw[w], snw[w], qns[q]);
        if (pass == 0) g_dis[w * QN + q0 + q] = d;
        else           outp[(size_t)(q0 + q) * WAYN + w] = -d * 0.0625f;
    }
}

// ---------------- K5: per-way top-10 via register-resident 64-bit keys ----------------
__global__ __launch_bounds__(512) void k_topk() {
    int w = blockIdx.x, t = threadIdx.x;
    int lane = t & 31, wid = t >> 5;
    const float* row = g_dis + w * QN;

    __shared__ float sred[16];
    __shared__ unsigned long long swin[16];
    __shared__ unsigned long long winner;

    unsigned long long k[8];
    float sum = 0.f;
#pragma unroll
    for (int i = 0; i < 8; i++) {
        int q = i * 512 + t;
        float x = row[q];
        sum += x;
        k[i] = ((unsigned long long)__float_as_uint(x) << 32) | (unsigned)q;
    }

#pragma unroll
    for (int i = 0; i < 8; i++)
#pragma unroll
        for (int j = 0; j < 7; j++) {
            if (j < 7 - i) {
                unsigned long long lo = (k[j] < k[j + 1]) ? k[j] : k[j + 1];
                unsigned long long hi = (k[j] < k[j + 1]) ? k[j + 1] : k[j];
                k[j] = lo; k[j + 1] = hi;
            }
        }

#pragma unroll
    for (int off = 16; off; off >>= 1) sum += __shfl_down_sync(0xffffffffu, sum, off);
    if (lane == 0) sred[wid] = sum;
    __syncthreads();
    if (t == 0) {
        float s = 0.f;
        for (int i = 0; i < 16; i++) s += sred[i];
        g_T[w] = s;
        float f = 0.f;
        for (int q = 0; q < RRN; q++) f += row[q];
        g_f10[w] = f;
    }

    for (int r = 0; r < RRN; r++) {
        unsigned long long m = k[0];
#pragma unroll
        for (int off = 16; off; off >>= 1) {
            unsigned long long o = __shfl_down_sync(0xffffffffu, m, off);
            if (o < m) m = o;
        }
        if (lane == 0) swin[wid] = m;
        __syncthreads();
        if (t < 16) {
            unsigned long long mm = swin[t];
#pragma unroll
            for (int off = 8; off; off >>= 1) {
                unsigned long long o = __shfl_down_sync(0x0000ffffu, mm, off);
                if (o < mm) mm = o;
            }
            if (t == 0) {
                winner = mm;
                g_nid[w * RRN + r]  = __uint_as_float((unsigned)(mm >> 32));
                g_nidx[w * RRN + r] = (int)(mm & 0xffffffffu);
            }
        }
        __syncthreads();
        if (k[0] == winner) {
#pragma unroll
            for (int i = 0; i < 7; i++) k[i] = k[i + 1];
            k[7] = 0xFFFFFFFFFFFFFFFFULL;
        }
    }
}

// ---------------- K6: stats + relation MLP -> i_w, onw ----------------
__global__ __launch_bounds__(1024) void k_small(const float* __restrict__ Wr1, const float* __restrict__ br1,
                                                const float* __restrict__ Wr2, const float* __restrict__ br2) {
    __shared__ float sT[32], sf10[32];
    __shared__ float snid[32][10];
    __shared__ int   sidx[32][10];
    __shared__ float scn[32][32];
    __shared__ float snod[32][10];
    int t = threadIdx.x;

    if (t < 32) { sT[t] = g_T[t]; sf10[t] = g_f10[t]; }
    if (t < 320) { int i = t / 10, kk = t % 10; snid[i][kk] = g_nid[t]; sidx[i][kk] = g_nidx[t]; }
    __syncthreads();

    {
        int i = t >> 5, j = t & 31;
        float s = 0.f;
        for (int kk = 0; kk < 10; kk++) s += g_dis[j * QN + sidx[i][kk]];
        scn[i][j] = s;
    }
    if (t < 320) {
        int i = t / 10, kk = t % 10;
        int q = sidx[i][kk];
        float s = 0.f;
        for (int j = 0; j < 32; j++) s += g_dis[j * QN + q];
        snod[i][kk] = (s - snid[i][kk]) * (1.0f / 31.0f);
    }
    __syncthreads();

    if (t < 32) {
        int i = t;
        float nsum = 0.f;
        for (int kk = 0; kk < 10; kk++) nsum += snid[i][kk];
        float oid = (sT[i] - nsum) * (1.0f / (float)(QN - RRN));
        float sa = 0.f;
        for (int j = 0; j < i; j++) sa += sT[j] - scn[i][j];
        float sb = 0.f;
        for (int j = i + 1; j < 32; j++) sb += sT[j] - sf10[j];
        float ood = (sa + sb) * (1.0f / (float)((WAYN - 1) * (QN - RRN)));

        float rin[22];
        for (int kk = 0; kk < 10; kk++) { rin[kk] = snid[i][kk]; rin[10 + kk] = snod[i][kk]; }
        rin[20] = oid; rin[21] = ood;

        float hr[10];
        for (int r = 0; r < 10; r++) {
            float a = br1[r];
            for (int d = 0; d < 22; d++) a = fmaf(rin[d], Wr1[d * 10 + r], a);
            hr[r] = fmaxf(a, 0.f);
        }
        float orr[11];
        for (int j = 0; j < 11; j++) {
            float a = br2[j];
            for (int r = 0; r < 10; r++) a = fmaf(hr[r], Wr2[r * 11 + j], a);
            orr[j] = a;
        }
        float m = orr[0];
        for (int kk = 1; kk < 10; kk++) m = fmaxf(m, orr[kk]);
        float e[10], se = 0.f;
        for (int kk = 0; kk < 10; kk++) { e[kk] = expf(orr[kk] - m); se += e[kk]; }
        for (int kk = 0; kk < 10; kk++) g_iw[i * 10 + kk] = e[kk] / se;
        g_onw[i] = 1.f / (1.f + expf(-orr[10]));
    }
}

// ---------------- K7: weighted query + test proto (transposed) + norm/scale ----------------
__global__ void k_wdq(const float* __restrict__ dq) {
    int w = blockIdx.x, t = threadIdx.x;
    __shared__ float iw[10];
    __shared__ int   id[10];
    __shared__ float red[256];
    if (t < 10) { iw[t] = g_iw[w * 10 + t]; id[t] = g_nidx[w * 10 + t]; }
    __syncthreads();
    float onw = g_onw[w];
    float om  = 1.f - onw;
    float4 wd = make_float4(0.f, 0.f, 0.f, 0.f);
#pragma unroll
    for (int kk = 0; kk < 10; kk++) {
        float4 qv = *((const float4*)(dq + (size_t)id[kk] * DIMN) + t);
        float wk = iw[kk];
        wd.x = fmaf(wk, qv.x, wd.x); wd.y = fmaf(wk, qv.y, wd.y);
        wd.z = fmaf(wk, qv.z, wd.z); wd.w = fmaf(wk, qv.w, wd.w);
    }
    float4 pv = *((const float4*)(g_protos + w * DIMN) + t);
    float4 tm;
    tm.x = pv.x * onw + wd.x * om;
    tm.y = pv.y * onw + wd.y * om;
    tm.z = pv.z * onw + wd.z * om;
    tm.w = pv.w * onw + wd.w * om;
    int d0 = t * 4;
    g_tmpT[(d0 + 0) * WAYN + w] = tm.x;
    g_tmpT[(d0 + 1) * WAYN + w] = tm.y;
    g_tmpT[(d0 + 2) * WAYN + w] = tm.z;
    g_tmpT[(d0 + 3) * WAYN + w] = tm.w;

    red[t] = tm.x * tm.x + tm.y * tm.y + tm.z * tm.z + tm.w * tm.w;
    if (t < 96) red[160 + t] = 0.f;
    __syncthreads();
    for (int o = 128; o; o >>= 1) { if (t < o) red[t] += red[t + o]; __syncthreads(); }
    if (t == 0) {
        float nt = sqrtf(red[0]);
        g_tn[w] = nt;
        g_st[w] = expmap_scale(nt, g_c[w]);
    }
}

// ---------------- launch ----------------
extern "C" void kernel_launch(void* const* d_in, const int* in_sizes, int n_in,
                              void* d_out, int out_size) {
    const float* ds  = (const float*)d_in[0];
    const float* dq  = (const float*)d_in[1];
    const float* W1  = (const float*)d_in[2];
    const float* b1  = (const float*)d_in[3];
    const float* W2  = (const float*)d_in[4];
    const float* b2  = (const float*)d_in[5];
    const float* W3  = (const float*)d_in[6];
    const float* b3  = (const float*)d_in[7];
    const float* Wr1 = (const float*)d_in[8];
    const float* br1 = (const float*)d_in[9];
    const float* Wr2 = (const float*)d_in[10];
    const float* br2 = (const float*)d_in[11];
    float* out = (float*)d_out;

    k_protos<<<32, 256>>>(ds);
    k_colsum<<<dim3(5, 16), 128>>>(ds, dq);
    k_ctrl<<<32, 128>>>(W1, b1, W2, b2, W3, b3);
    k_gemm_dist<<<128, 256>>>(dq, out, 0);
    k_topk<<<32, 512>>>();
    k_small<<<1, 1024>>>(Wr1, br1, Wr2, br2);
    k_wdq<<<32, 160>>>(dq);
    k_gemm_dist<<<128, 256>>>(dq, out, 1);
}

// round 10
// speedup vs baseline: 1.5779x; 1.0225x over previous
#include <cuda_runtime.h>

#define EPSF 1e-5f

static constexpr int WAYN = 32;
static constexpr int QN   = 4096;
static constexpr int DIMN = 640;
static constexpr int RRN  = 10;

// ---------------- scratch (device globals; no allocation) ----------------
__device__ float g_protos[WAYN * DIMN];
__device__ float g_protosT[DIMN * WAYN];   // [k][w]
__device__ float g_pn[WAYN];
__device__ float g_part[16 * DIMN];
__device__ float g_c[WAYN];
__device__ float g_sp[WAYN];
__device__ float g_dis[WAYN * QN];
__device__ float g_T[WAYN];
__device__ float g_f10[WAYN];
__device__ float g_nid[WAYN * RRN];
__device__ int   g_nidx[WAYN * RRN];
__device__ float g_iw[WAYN * RRN];
__device__ float g_onw[WAYN];
__device__ float g_tmpT[DIMN * WAYN];      // [k][w]
__device__ float g_tn[WAYN];
__device__ float g_st[WAYN];

// ---------------- math helpers ----------------
__device__ __forceinline__ float expmap_scale(float nx, float c) {
    float sc = sqrtf(c);
    float n  = fmaxf(nx, EPSF);
    float th = tanhf(sc * n);
    float s  = th / (sc * n);
    float ny = fmaxf(s * nx, EPSF);
    float maxn = 0.999f / sc;
    if (ny > maxn) s *= maxn / ny;
    return s;
}

__device__ __forceinline__ float pdist(float G, float c, float sp, float np_, float nq) {
    float sc = sqrtf(c);
    float sq = expmap_scale(nq, c);
    float xy = sp * sq * G;
    float uy = -xy;
    float u2 = sp * sp * np_ * np_;
    float y2 = sq * sq * nq * nq;
    float A  = 1.f + 2.f * c * uy + c * y2;
    float B  = 1.f - c * u2;
    float num2 = A * A * u2 + 2.f * A * B * uy + B * B * y2;
    float den  = fmaxf(1.f + 2.f * c * uy + c * c * u2 * y2, EPSF);
    float nn   = sqrtf(fmaxf(num2, 0.f)) / den;
    float arg  = fminf(sc * nn, 1.f - EPSF);
    arg = fmaxf(arg, 0.f);
    return (2.f / sc) * atanhf(arg);
}

// ---------------- K1: protos + transpose + proto norms ----------------
__global__ void k_protos(const float* __restrict__ ds) {
    int w = blockIdx.x, t = threadIdx.x;
    __shared__ float red[256];
    float acc = 0.f;
    for (int d = t; d < DIMN; d += 256) {
        float s = 0.f;
#pragma unroll
        for (int sh = 0; sh < 5; sh++) s += ds[(sh * WAYN + w) * DIMN + d];
        float p = s * 0.2f;
        g_protos[w * DIMN + d] = p;
        g_protosT[d * WAYN + w] = p;
        acc += p * p;
    }
    red[t] = acc;
    __syncthreads();
    for (int o = 128; o; o >>= 1) { if (t < o) red[t] += red[t + o]; __syncthreads(); }
    if (t == 0) g_pn[w] = sqrtf(red[0]);
}

// ---------------- K2: deterministic column partial-sums for all_data ----------------
__global__ void k_colsum(const float* __restrict__ ds, const float* __restrict__ dq) {
    int c = blockIdx.x * 128 + threadIdx.x;
    int p = blockIdx.y;
    int r0 = p * 266, r1 = min(r0 + 266, 4256);
    float acc = 0.f;
    for (int r = r0; r < r1; r++)
        acc += (r < 160) ? ds[r * DIMN + c] : dq[(size_t)(r - 160) * DIMN + c];
    g_part[p * DIMN + c] = acc;
}

// ---------------- K3: controller MLP (k-split) -> c[w], proto scale sp[w] ----------------
__global__ __launch_bounds__(256) void k_ctrl(const float* __restrict__ W1, const float* __restrict__ b1,
                                              const float* __restrict__ W2, const float* __restrict__ b2,
                                              const float* __restrict__ W3, const float* __restrict__ b3) {
    int w = blockIdx.x, t = threadIdx.x;
    __shared__ float ci[2 * DIMN];
    __shared__ float hpart[256];
    __shared__ float h1[128];
    __shared__ float h2[64];
    for (int d = t; d < DIMN; d += 256) {
        ci[d] = g_protos[w * DIMN + d];
        float s = 0.f;
#pragma unroll
        for (int p = 0; p < 16; p++) s += g_part[p * DIMN + d];
        ci[DIMN + d] = s * (1.0f / 4256.0f);
    }
    __syncthreads();
    {
        int o = t & 127, hf = t >> 7;
        const float* wp = W1 + (size_t)(hf * DIMN) * 128 + o;
        const float* cp = ci + hf * DIMN;
        float a0 = 0.f, a1 = 0.f, a2 = 0.f, a3 = 0.f;
#pragma unroll 4
        for (int d = 0; d < DIMN; d += 4) {
            a0 = fmaf(cp[d + 0], wp[(d + 0) * 128], a0);
            a1 = fmaf(cp[d + 1], wp[(d + 1) * 128], a1);
            a2 = fmaf(cp[d + 2], wp[(d + 2) * 128], a2);
            a3 = fmaf(cp[d + 3], wp[(d + 3) * 128], a3);
        }
        hpart[t] = (a0 + a1) + (a2 + a3);
    }
    __syncthreads();
    if (t < 128) h1[t] = fmaxf(hpart[t] + hpart[t + 128] + b1[t], 0.f);
    __syncthreads();
    if (t < 64) {
        float a = b2[t];
#pragma unroll 4
        for (int d = 0; d < 128; d++) a = fmaf(h1[d], W2[d * 64 + t], a);
        h2[t] = fmaxf(a, 0.f);
    }
    __syncthreads();
    if (t == 0) {
        float lg[5];
        for (int o = 0; o < 5; o++) {
            float a = b3[o];
            for (int d = 0; d < 64; d++) a = fmaf(h2[d], W3[d * 5 + o], a);
            lg[o] = a;
        }
        float m = lg[0];
        for (int o = 1; o < 5; o++) m = fmaxf(m, lg[o]);
        float se = 0.f, cv = 0.f;
        for (int o = 0; o < 5; o++) {
            float e = expf(lg[o] - m);
            se += e;
            cv += e * ((float)(o + 1) * 0.2f);
        }
        float c = cv / se;
        g_c[w]  = c;
        g_sp[w] = expmap_scale(g_pn[w], c);
    }
}

// ---------------- K4/K8: GEMM (32w x 16q tile, grid 256) + distance epilogue ----------------
// A pre-transposed [640][32]. 8 k-slices x 32 threads; per k-step per thread:
// 1 LDS.128 (A, broadcast) + 4 scalar LDS (B, broadcast) + 16 FMA.
// Double-buffered smem, 1 barrier per 64-k chunk. ~25KB smem -> 2 blocks/SM.
#define STS_TILE(buf_)                                                            \
    do {                                                                          \
        *(float4*)&sm[(buf_) * 2048 + akr * 32 + aw4 * 4]        = ra0;           \
        *(float4*)&sm[(buf_) * 2048 + (akr + 32) * 32 + aw4 * 4] = ra1;           \
        int bb_ = 4096 + (buf_) * 1040;                                           \
        sm[bb_ + bqr * 65 + bk4 * 4 + 0] = rb0.x;                                 \
        sm[bb_ + bqr * 65 + bk4 * 4 + 1] = rb0.y;                                 \
        sm[bb_ + bqr * 65 + bk4 * 4 + 2] = rb0.z;                                 \
        sm[bb_ + bqr * 65 + bk4 * 4 + 3] = rb0.w;                                 \
    } while (0)

__global__ __launch_bounds__(256) void k_gemm_dist(const float* __restrict__ Bq,
                                                   float* __restrict__ outp, int pass) {
    const float* __restrict__ AT  = pass ? g_tmpT : g_protosT;
    const float* __restrict__ An  = pass ? g_tn   : g_pn;
    const float* __restrict__ Asc = pass ? g_st   : g_sp;

    __shared__ float sm[2 * 2048 + 2 * 1040];   // A dbl (64x32) | B dbl (16x65); Rs aliased
    __shared__ float qns[16], scw[32], snw[32], ssw[32];

    int t = threadIdx.x;
    int q0 = blockIdx.x * 16;

    if (t < 32) { scw[t] = g_c[t]; snw[t] = An[t]; ssw[t] = Asc[t]; }

    int aw4 = t & 7, akr = t >> 3;      // A loader: 32 k-rows x 8 w-float4 (2 rows each)
    int bk4 = t & 15, bqr = t >> 4;     // B loader: 16 q-rows x 16 k-float4

    const float* aptr = AT + akr * 32 + aw4 * 4;
    const float* bptr = Bq + (size_t)(q0 + bqr) * DIMN + bk4 * 4;

    float4 ra0, ra1, rb0;
    float q2 = 0.f;

    ra0 = *(const float4*)(aptr);
    ra1 = *(const float4*)(aptr + 32 * 32);
    rb0 = *(const float4*)(bptr);
    q2 += rb0.x * rb0.x + rb0.y * rb0.y + rb0.z * rb0.z + rb0.w * rb0.w;

    STS_TILE(0);
    __syncthreads();

    float acc[4][4];
#pragma unroll
    for (int i = 0; i < 4; i++)
#pragma unroll
        for (int j = 0; j < 4; j++) acc[i][j] = 0.f;

    int slice = t >> 5;                 // 8 k-slices (one warp each)
    int ct = t & 31;
    int wt = ct & 7;                    // 8 x 4w
    int qt = ct >> 3;                   // 4 x 4q
    int kb = slice * 8;

    for (int c = 0; c < 10; c++) {
        int cur = c & 1;
        if (c < 9) {
            const float* ap = aptr + (c + 1) * 64 * 32;
            ra0 = *(const float4*)(ap);
            ra1 = *(const float4*)(ap + 32 * 32);
            rb0 = *(const float4*)(bptr + (c + 1) * 64);
            q2 += rb0.x * rb0.x + rb0.y * rb0.y + rb0.z * rb0.z + rb0.w * rb0.w;
        }
        const float* Asb = sm + cur * 2048;
        const float* Bsb = sm + 4096 + cur * 1040;
#pragma unroll
        for (int kk = 0; kk < 8; kk++) {
            int k = kb + kk;
            float4 a = *(const float4*)&Asb[k * 32 + wt * 4];
            float b0 = Bsb[(qt * 4 + 0) * 65 + k];
            float b1 = Bsb[(qt * 4 + 1) * 65 + k];
            float b2 = Bsb[(qt * 4 + 2) * 65 + k];
            float b3 = Bsb[(qt * 4 + 3) * 65 + k];
            acc[0][0] = fmaf(a.x, b0, acc[0][0]); acc[0][1] = fmaf(a.x, b1, acc[0][1]);
            acc[0][2] = fmaf(a.x, b2, acc[0][2]); acc[0][3] = fmaf(a.x, b3, acc[0][3]);
            acc[1][0] = fmaf(a.y, b0, acc[1][0]); acc[1][1] = fmaf(a.y, b1, acc[1][1]);
            acc[1][2] = fmaf(a.y, b2, acc[1][2]); acc[1][3] = fmaf(a.y, b3, acc[1][3]);
            acc[2][0] = fmaf(a.z, b0, acc[2][0]); acc[2][1] = fmaf(a.z, b1, acc[2][1]);
            acc[2][2] = fmaf(a.z, b2, acc[2][2]); acc[2][3] = fmaf(a.z, b3, acc[2][3]);
            acc[3][0] = fmaf(a.w, b0, acc[3][0]); acc[3][1] = fmaf(a.w, b1, acc[3][1]);
            acc[3][2] = fmaf(a.w, b2, acc[3][2]); acc[3][3] = fmaf(a.w, b3, acc[3][3]);
        }
        if (c < 9) {
            STS_TILE((c + 1) & 1);
            __syncthreads();
        }
    }

    // query norms: 16 loader lanes per q-row (contiguous 16-lane groups)
#pragma unroll
    for (int off = 8; off >= 1; off >>= 1)
        q2 += __shfl_down_sync(0xffffffffu, q2, off, 16);
    if ((t & 15) == 0) qns[bqr] = sqrtf(q2);

    __syncthreads();          // tiles dead; alias Rs onto sm (8 slices x 32x17 = 4352 floats)
    float* Rs = sm;
#pragma unroll
    for (int i = 0; i < 4; i++)
#pragma unroll
        for (int j = 0; j < 4; j++)
            Rs[slice * 544 + (wt * 4 + i) * 17 + (qt * 4 + j)] = acc[i][j];
    __syncthreads();

#pragma unroll
    for (int r = 0; r < 2; r++) {
        int idx = r * 256 + t;          // 512 outputs
        int w, q;
        if (pass == 0) { w = idx >> 4; q = idx & 15; }
        else           { w = idx & 31; q = idx >> 5; }
        int o = w * 17 + q;
        float G = 0.f;
#pragma unroll
        for (int s = 0; s < 8; s++) G += Rs[s * 544 + o];
        float d = pdist(G, scw[w], ssw[w], snw[w], qns[q]);
        if (pass == 0) g_dis[w * QN + q0 + q] = d;
        else           outp[(size_t)(q0 + q) * WAYN + w] = -d * 0.0625f;
    }
}

// ---------------- K5: per-way top-10 via register-resident 64-bit keys ----------------
__global__ __launch_bounds__(512) void k_topk() {
    int w = blockIdx.x, t = threadIdx.x;
    int lane = t & 31, wid = t >> 5;
    const float* row = g_dis + w * QN;

    __shared__ float sred[16];
    __shared__ unsigned long long swin[16];
    __shared__ unsigned long long winner;

    unsigned long long k[8];
    float sum = 0.f;
#pragma unroll
    for (int i = 0; i < 8; i++) {
        int q = i * 512 + t;
        float x = row[q];
        sum += x;
        k[i] = ((unsigned long long)__float_as_uint(x) << 32) | (unsigned)q;
    }

#pragma unroll
    for (int i = 0; i < 8; i++)
#pragma unroll
        for (int j = 0; j < 7; j++) {
            if (j < 7 - i) {
                unsigned long long lo = (k[j] < k[j + 1]) ? k[j] : k[j + 1];
                unsigned long long hi = (k[j] < k[j + 1]) ? k[j + 1] : k[j];
                k[j] = lo; k[j + 1] = hi;
            }
        }

#pragma unroll
    for (int off = 16; off; off >>= 1) sum += __shfl_down_sync(0xffffffffu, sum, off);
    if (lane == 0) sred[wid] = sum;
    __syncthreads();
    if (t == 0) {
        float s = 0.f;
        for (int i = 0; i < 16; i++) s += sred[i];
        g_T[w] = s;
        float f = 0.f;
        for (int q = 0; q < RRN; q++) f += row[q];
        g_f10[w] = f;
    }

    for (int r = 0; r < RRN; r++) {
        unsigned long long m = k[0];
#pragma unroll
        for (int off = 16; off; off >>= 1) {
            unsigned long long o = __shfl_down_sync(0xffffffffu, m, off);
            if (o < m) m = o;
        }
        if (lane == 0) swin[wid] = m;
        __syncthreads();
        if (t < 16) {
            unsigned long long mm = swin[t];
#pragma unroll
            for (int off = 8; off; off >>= 1) {
                unsigned long long o = __shfl_down_sync(0x0000ffffu, mm, off);
                if (o < mm) mm = o;
            }
            if (t == 0) {
                winner = mm;
                g_nid[w * RRN + r]  = __uint_as_float((unsigned)(mm >> 32));
                g_nidx[w * RRN + r] = (int)(mm & 0xffffffffu);
            }
        }
        __syncthreads();
        if (k[0] == winner) {
#pragma unroll
            for (int i = 0; i < 7; i++) k[i] = k[i + 1];
            k[7] = 0xFFFFFFFFFFFFFFFFULL;
        }
    }
}

// ---------------- K6: stats + relation MLP -> i_w, onw ----------------
__global__ __launch_bounds__(1024) void k_small(const float* __restrict__ Wr1, const float* __restrict__ br1,
                                                const float* __restrict__ Wr2, const float* __restrict__ br2) {
    __shared__ float sT[32], sf10[32];
    __shared__ float snid[32][10];
    __shared__ int   sidx[32][10];
    __shared__ float scn[32][32];
    __shared__ float snod[32][10];
    int t = threadIdx.x;

    if (t < 32) { sT[t] = g_T[t]; sf10[t] = g_f10[t]; }
    if (t < 320) { int i = t / 10, kk = t % 10; snid[i][kk] = g_nid[t]; sidx[i][kk] = g_nidx[t]; }
    __syncthreads();

    {
        int i = t >> 5, j = t & 31;
        float s = 0.f;
        for (int kk = 0; kk < 10; kk++) s += g_dis[j * QN + sidx[i][kk]];
        scn[i][j] = s;
    }
    if (t < 320) {
        int i = t / 10, kk = t % 10;
        int q = sidx[i][kk];
        float s = 0.f;
        for (int j = 0; j < 32; j++) s += g_dis[j * QN + q];
        snod[i][kk] = (s - snid[i][kk]) * (1.0f / 31.0f);
    }
    __syncthreads();

    if (t < 32) {
        int i = t;
        float nsum = 0.f;
        for (int kk = 0; kk < 10; kk++) nsum += snid[i][kk];
        float oid = (sT[i] - nsum) * (1.0f / (float)(QN - RRN));
        float sa = 0.f;
        for (int j = 0; j < i; j++) sa += sT[j] - scn[i][j];
        float sb = 0.f;
        for (int j = i + 1; j < 32; j++) sb += sT[j] - sf10[j];
        float ood = (sa + sb) * (1.0f / (float)((WAYN - 1) * (QN - RRN)));

        float rin[22];
        for (int kk = 0; kk < 10; kk++) { rin[kk] = snid[i][kk]; rin[10 + kk] = snod[i][kk]; }
        rin[20] = oid; rin[21] = ood;

        float hr[10];
        for (int r = 0; r < 10; r++) {
            float a = br1[r];
            for (int d = 0; d < 22; d++) a = fmaf(rin[d], Wr1[d * 10 + r], a);
            hr[r] = fmaxf(a, 0.f);
        }
        float orr[11];
        for (int j = 0; j < 11; j++) {
            float a = br2[j];
            for (int r = 0; r < 10; r++) a = fmaf(hr[r], Wr2[r * 11 + j], a);
            orr[j] = a;
        }
        float m = orr[0];
        for (int kk = 1; kk < 10; kk++) m = fmaxf(m, orr[kk]);
        float e[10], se = 0.f;
        for (int kk = 0; kk < 10; kk++) { e[kk] = expf(orr[kk] - m); se += e[kk]; }
        for (int kk = 0; kk < 10; kk++) g_iw[i * 10 + kk] = e[kk] / se;
        g_onw[i] = 1.f / (1.f + expf(-orr[10]));
    }
}

// ---------------- K7: weighted query + test proto (transposed) + norm/scale ----------------
__global__ void k_wdq(const float* __restrict__ dq) {
    int w = blockIdx.x, t = threadIdx.x;
    __shared__ float iw[10];
    __shared__ int   id[10];
    __shared__ float red[256];
    if (t < 10) { iw[t] = g_iw[w * 10 + t]; id[t] = g_nidx[w * 10 + t]; }
    __syncthreads();
    float onw = g_onw[w];
    float om  = 1.f - onw;
    float4 wd = make_float4(0.f, 0.f, 0.f, 0.f);
#pragma unroll
    for (int kk = 0; kk < 10; kk++) {
        float4 qv = *((const float4*)(dq + (size_t)id[kk] * DIMN) + t);
        float wk = iw[kk];
        wd.x = fmaf(wk, qv.x, wd.x); wd.y = fmaf(wk, qv.y, wd.y);
        wd.z = fmaf(wk, qv.z, wd.z); wd.w = fmaf(wk, qv.w, wd.w);
    }
    float4 pv = *((const float4*)(g_protos + w * DIMN) + t);
    float4 tm;
    tm.x = pv.x * onw + wd.x * om;
    tm.y = pv.y * onw + wd.y * om;
    tm.z = pv.z * onw + wd.z * om;
    tm.w = pv.w * onw + wd.w * om;
    int d0 = t * 4;
    g_tmpT[(d0 + 0) * WAYN + w] = tm.x;
    g_tmpT[(d0 + 1) * WAYN + w] = tm.y;
    g_tmpT[(d0 + 2) * WAYN + w] = tm.z;
    g_tmpT[(d0 + 3) * WAYN + w] = tm.w;

    red[t] = tm.x * tm.x + tm.y * tm.y + tm.z * tm.z + tm.w * tm.w;
    if (t < 96) red[160 + t] = 0.f;
    __syncthreads();
    for (int o = 128; o; o >>= 1) { if (t < o) red[t] += red[t + o]; __syncthreads(); }
    if (t == 0) {
        float nt = sqrtf(red[0]);
        g_tn[w] = nt;
        g_st[w] = expmap_scale(nt, g_c[w]);
    }
}

// ---------------- launch ----------------
extern "C" void kernel_launch(void* const* d_in, const int* in_sizes, int n_in,
                              void* d_out, int out_size) {
    const float* ds  = (const float*)d_in[0];
    const float* dq  = (const float*)d_in[1];
    const float* W1  = (const float*)d_in[2];
    const float* b1  = (const float*)d_in[3];
    const float* W2  = (const float*)d_in[4];
    const float* b2  = (const float*)d_in[5];
    const float* W3  = (const float*)d_in[6];
    const float* b3  = (const float*)d_in[7];
    const float* Wr1 = (const float*)d_in[8];
    const float* br1 = (const float*)d_in[9];
    const float* Wr2 = (const float*)d_in[10];
    const float* br2 = (const float*)d_in[11];
    float* out = (float*)d_out;

    k_protos<<<32, 256>>>(ds);
    k_colsum<<<dim3(5, 16), 128>>>(ds, dq);
    k_ctrl<<<32, 256>>>(W1, b1, W2, b2, W3, b3);
    k_gemm_dist<<<256, 256>>>(dq, out, 0);
    k_topk<<<32, 512>>>();
    k_small<<<1, 1024>>>(Wr1, br1, Wr2, br2);
    k_wdq<<<32, 160>>>(dq);
    k_gemm_dist<<<256, 256>>>(dq, out, 1);
}

// round 14
// speedup vs baseline: 1.7349x; 1.0995x over previous
#include <cuda_runtime.h>

#define EPSF 1e-5f

static constexpr int WAYN = 32;
static constexpr int QN   = 4096;
static constexpr int DIMN = 640;
static constexpr int RRN  = 10;
static constexpr int NPART = 128;          // colsum row-partials
static constexpr int ROWS_TOTAL = 4256;    // 160 shot + 4096 query
static constexpr int ROWS_PER_P = 34;      // ceil(4256/128)

// ---------------- scratch (device globals; no allocation) ----------------
__device__ float g_protos[WAYN * DIMN];
__device__ float g_protosT[DIMN * WAYN];   // [k][w]
__device__ float g_pn[WAYN];
__device__ float g_part[NPART * DIMN];
__device__ float g_c[WAYN];
__device__ float g_sp[WAYN];
__device__ float g_dis[WAYN * QN];
__device__ float g_T[WAYN];
__device__ float g_f10[WAYN];
__device__ float g_nid[WAYN * RRN];
__device__ int   g_nidx[WAYN * RRN];
__device__ float g_iw[WAYN * RRN];
__device__ float g_onw[WAYN];
__device__ float g_tmpT[DIMN * WAYN];      // [k][w]
__device__ float g_tn[WAYN];
__device__ float g_st[WAYN];

// ---------------- math helpers ----------------
__device__ __forceinline__ float expmap_scale(float nx, float c) {
    float sc = sqrtf(c);
    float n  = fmaxf(nx, EPSF);
    float th = tanhf(sc * n);
    float s  = th / (sc * n);
    float ny = fmaxf(s * nx, EPSF);
    float maxn = 0.999f / sc;
    if (ny > maxn) s *= maxn / ny;
    return s;
}

__device__ __forceinline__ float pdist(float G, float c, float sp, float np_, float nq) {
    float sc = sqrtf(c);
    float sq = expmap_scale(nq, c);
    float xy = sp * sq * G;
    float uy = -xy;
    float u2 = sp * sp * np_ * np_;
    float y2 = sq * sq * nq * nq;
    float A  = 1.f + 2.f * c * uy + c * y2;
    float B  = 1.f - c * u2;
    float num2 = A * A * u2 + 2.f * A * B * uy + B * B * y2;
    float den  = fmaxf(1.f + 2.f * c * uy + c * c * u2 * y2, EPSF);
    float nn   = sqrtf(fmaxf(num2, 0.f)) / den;
    float arg  = fminf(sc * nn, 1.f - EPSF);
    arg = fmaxf(arg, 0.f);
    return (2.f / sc) * atanhf(arg);
}

// ---------------- K1: fused protos(+transpose,+norm) and coalesced column partials ----
__global__ __launch_bounds__(256) void k_pre(const float* __restrict__ ds,
                                             const float* __restrict__ dq) {
    int b = blockIdx.x, t = threadIdx.x;
    if (b < 32) {
        int w = b;
        __shared__ float red[256];
        float acc = 0.f;
        for (int d = t; d < DIMN; d += 256) {
            float s = 0.f;
#pragma unroll
            for (int sh = 0; sh < 5; sh++) s += ds[(sh * WAYN + w) * DIMN + d];
            float p = s * 0.2f;
            g_protos[w * DIMN + d] = p;
            g_protosT[d * WAYN + w] = p;
            acc += p * p;
        }
        red[t] = acc;
        __syncthreads();
        for (int o = 128; o; o >>= 1) { if (t < o) red[t] += red[t + o]; __syncthreads(); }
        if (t == 0) g_pn[w] = sqrtf(red[0]);
    } else {
        // column partial sums: partial p covers rows [p*34, min(+34, 4256))
        int p = b - 32;
        int r0 = p * ROWS_PER_P;
        int r1 = min(r0 + ROWS_PER_P, ROWS_TOTAL);
        for (int c = t; c < DIMN; c += 256) {
            float a0 = 0.f, a1 = 0.f, a2 = 0.f, a3 = 0.f;
            int r = r0;
            for (; r + 4 <= r1; r += 4) {
                float v0 = (r + 0 < 160) ? ds[(r + 0) * DIMN + c] : dq[(size_t)(r + 0 - 160) * DIMN + c];
                float v1 = (r + 1 < 160) ? ds[(r + 1) * DIMN + c] : dq[(size_t)(r + 1 - 160) * DIMN + c];
                float v2 = (r + 2 < 160) ? ds[(r + 2) * DIMN + c] : dq[(size_t)(r + 2 - 160) * DIMN + c];
                float v3 = (r + 3 < 160) ? ds[(r + 3) * DIMN + c] : dq[(size_t)(r + 3 - 160) * DIMN + c];
                a0 += v0; a1 += v1; a2 += v2; a3 += v3;
            }
            for (; r < r1; r++)
                a0 += (r < 160) ? ds[r * DIMN + c] : dq[(size_t)(r - 160) * DIMN + c];
            g_part[p * DIMN + c] = (a0 + a1) + (a2 + a3);
        }
    }
}

// ---------------- K3: controller MLP (k-split) -> c[w], proto scale sp[w] ----------------
__global__ __launch_bounds__(256) void k_ctrl(const float* __restrict__ W1, const float* __restrict__ b1,
                                              const float* __restrict__ W2, const float* __restrict__ b2,
                                              const float* __restrict__ W3, const float* __restrict__ b3) {
    int w = blockIdx.x, t = threadIdx.x;
    __shared__ float ci[2 * DIMN];
    __shared__ float hpart[256];
    __shared__ float h1[128];
    __shared__ float h2[64];
    for (int d = t; d < DIMN; d += 256) {
        ci[d] = g_protos[w * DIMN + d];
        float s0 = 0.f, s1 = 0.f, s2 = 0.f, s3 = 0.f;
#pragma unroll 4
        for (int p = 0; p < NPART; p += 4) {
            s0 += g_part[(p + 0) * DIMN + d];
            s1 += g_part[(p + 1) * DIMN + d];
            s2 += g_part[(p + 2) * DIMN + d];
            s3 += g_part[(p + 3) * DIMN + d];
        }
        ci[DIMN + d] = ((s0 + s1) + (s2 + s3)) * (1.0f / 4256.0f);
    }
    __syncthreads();
    {
        int o = t & 127, hf = t >> 7;
        const float* wp = W1 + (size_t)(hf * DIMN) * 128 + o;
        const float* cp = ci + hf * DIMN;
        float a0 = 0.f, a1 = 0.f, a2 = 0.f, a3 = 0.f;
#pragma unroll 4
        for (int d = 0; d < DIMN; d += 4) {
            a0 = fmaf(cp[d + 0], wp[(d + 0) * 128], a0);
            a1 = fmaf(cp[d + 1], wp[(d + 1) * 128], a1);
            a2 = fmaf(cp[d + 2], wp[(d + 2) * 128], a2);
            a3 = fmaf(cp[d + 3], wp[(d + 3) * 128], a3);
        }
        hpart[t] = (a0 + a1) + (a2 + a3);
    }
    __syncthreads();
    if (t < 128) h1[t] = fmaxf(hpart[t] + hpart[t + 128] + b1[t], 0.f);
    __syncthreads();
    if (t < 64) {
        float a = b2[t];
#pragma unroll 4
        for (int d = 0; d < 128; d++) a = fmaf(h1[d], W2[d * 64 + t], a);
        h2[t] = fmaxf(a, 0.f);
    }
    __syncthreads();
    if (t == 0) {
        float lg[5];
        for (int o = 0; o < 5; o++) {
            float a = b3[o];
            for (int d = 0; d < 64; d++) a = fmaf(h2[d], W3[d * 5 + o], a);
            lg[o] = a;
        }
        float m = lg[0];
        for (int o = 1; o < 5; o++) m = fmaxf(m, lg[o]);
        float se = 0.f, cv = 0.f;
        for (int o = 0; o < 5; o++) {
            float e = expf(lg[o] - m);
            se += e;
            cv += e * ((float)(o + 1) * 0.2f);
        }
        float c = cv / se;
        g_c[w]  = c;
        g_sp[w] = expmap_scale(g_pn[w], c);
    }
}

// ---------------- K4/K8: GEMM (32w x 16q tile, grid 256) + distance epilogue ----------------
#define STS_TILE(buf_)                                                            \
    do {                                                                          \
        *(float4*)&sm[(buf_) * 2048 + akr * 32 + aw4 * 4]        = ra0;           \
        *(float4*)&sm[(buf_) * 2048 + (akr + 32) * 32 + aw4 * 4] = ra1;           \
        int bb_ = 4096 + (buf_) * 1040;                                           \
        sm[bb_ + bqr * 65 + bk4 * 4 + 0] = rb0.x;                                 \
        sm[bb_ + bqr * 65 + bk4 * 4 + 1] = rb0.y;                                 \
        sm[bb_ + bqr * 65 + bk4 * 4 + 2] = rb0.z;                                 \
        sm[bb_ + bqr * 65 + bk4 * 4 + 3] = rb0.w;                                 \
    } while (0)

__global__ __launch_bounds__(256) void k_gemm_dist(const float* __restrict__ Bq,
                                                   float* __restrict__ outp, int pass) {
    const float* __restrict__ AT  = pass ? g_tmpT : g_protosT;
    const float* __restrict__ An  = pass ? g_tn   : g_pn;
    const float* __restrict__ Asc = pass ? g_st   : g_sp;

    __shared__ float sm[2 * 2048 + 2 * 1040];
    __shared__ float qns[16], scw[32], snw[32], ssw[32];

    int t = threadIdx.x;
    int q0 = blockIdx.x * 16;

    if (t < 32) { scw[t] = g_c[t]; snw[t] = An[t]; ssw[t] = Asc[t]; }

    int aw4 = t & 7, akr = t >> 3;
    int bk4 = t & 15, bqr = t >> 4;

    const float* aptr = AT + akr * 32 + aw4 * 4;
    const float* bptr = Bq + (size_t)(q0 + bqr) * DIMN + bk4 * 4;

    float4 ra0, ra1, rb0;
    float q2 = 0.f;

    ra0 = *(const float4*)(aptr);
    ra1 = *(const float4*)(aptr + 32 * 32);
    rb0 = *(const float4*)(bptr);
    q2 += rb0.x * rb0.x + rb0.y * rb0.y + rb0.z * rb0.z + rb0.w * rb0.w;

    STS_TILE(0);
    __syncthreads();

    float acc[4][4];
#pragma unroll
    for (int i = 0; i < 4; i++)
#pragma unroll
        for (int j = 0; j < 4; j++) acc[i][j] = 0.f;

    int slice = t >> 5;
    int ct = t & 31;
    int wt = ct & 7;
    int qt = ct >> 3;
    int kb = slice * 8;

    for (int c = 0; c < 10; c++) {
        int cur = c & 1;
        if (c < 9) {
            const float* ap = aptr + (c + 1) * 64 * 32;
            ra0 = *(const float4*)(ap);
            ra1 = *(const float4*)(ap + 32 * 32);
            rb0 = *(const float4*)(bptr + (c + 1) * 64);
            q2 += rb0.x * rb0.x + rb0.y * rb0.y + rb0.z * rb0.z + rb0.w * rb0.w;
        }
        const float* Asb = sm + cur * 2048;
        const float* Bsb = sm + 4096 + cur * 1040;
#pragma unroll
        for (int kk = 0; kk < 8; kk++) {
            int k = kb + kk;
            float4 a = *(const float4*)&Asb[k * 32 + wt * 4];
            float b0 = Bsb[(qt * 4 + 0) * 65 + k];
            float b1 = Bsb[(qt * 4 + 1) * 65 + k];
            float b2 = Bsb[(qt * 4 + 2) * 65 + k];
            float b3 = Bsb[(qt * 4 + 3) * 65 + k];
            acc[0][0] = fmaf(a.x, b0, acc[0][0]); acc[0][1] = fmaf(a.x, b1, acc[0][1]);
            acc[0][2] = fmaf(a.x, b2, acc[0][2]); acc[0][3] = fmaf(a.x, b3, acc[0][3]);
            acc[1][0] = fmaf(a.y, b0, acc[1][0]); acc[1][1] = fmaf(a.y, b1, acc[1][1]);
            acc[1][2] = fmaf(a.y, b2, acc[1][2]); acc[1][3] = fmaf(a.y, b3, acc[1][3]);
            acc[2][0] = fmaf(a.z, b0, acc[2][0]); acc[2][1] = fmaf(a.z, b1, acc[2][1]);
            acc[2][2] = fmaf(a.z, b2, acc[2][2]); acc[2][3] = fmaf(a.z, b3, acc[2][3]);
            acc[3][0] = fmaf(a.w, b0, acc[3][0]); acc[3][1] = fmaf(a.w, b1, acc[3][1]);
            acc[3][2] = fmaf(a.w, b2, acc[3][2]); acc[3][3] = fmaf(a.w, b3, acc[3][3]);
        }
        if (c < 9) {
            STS_TILE((c + 1) & 1);
            __syncthreads();
        }
    }

#pragma unroll
    for (int off = 8; off >= 1; off >>= 1)
        q2 += __shfl_down_sync(0xffffffffu, q2, off, 16);
    if ((t & 15) == 0) qns[bqr] = sqrtf(q2);

    __syncthreads();
    float* Rs = sm;
#pragma unroll
    for (int i = 0; i < 4; i++)
#pragma unroll
        for (int j = 0; j < 4; j++)
            Rs[slice * 544 + (wt * 4 + i) * 17 + (qt * 4 + j)] = acc[i][j];
    __syncthreads();

#pragma unroll
    for (int r = 0; r < 2; r++) {
        int idx = r * 256 + t;
        int w, q;
        if (pass == 0) { w = idx >> 4; q = idx & 15; }
        else           { w = idx & 31; q = idx >> 5; }
        int o = w * 17 + q;
        float G = 0.f;
#pragma unroll
        for (int s = 0; s < 8; s++) G += Rs[s * 544 + o];
        float d = pdist(G, scw[w], ssw[w], snw[w], qns[q]);
        if (pass == 0) g_dis[w * QN + q0 + q] = d;
        else           outp[(size_t)(q0 + q) * WAYN + w] = -d * 0.0625f;
    }
}

// ---------------- K5: per-way top-10 via register-resident 64-bit keys ----------------
__global__ __launch_bounds__(512) void k_topk() {
    int w = blockIdx.x, t = threadIdx.x;
    int lane = t & 31, wid = t >> 5;
    const float* row = g_dis + w * QN;

    __shared__ float sred[16];
    __shared__ unsigned long long swin[16];
    __shared__ unsigned long long winner;

    unsigned long long k[8];
    float sum = 0.f;
#pragma unroll
    for (int i = 0; i < 8; i++) {
        int q = i * 512 + t;
        float x = row[q];
        sum += x;
        k[i] = ((unsigned long long)__float_as_uint(x) << 32) | (unsigned)q;
    }

#pragma unroll
    for (int i = 0; i < 8; i++)
#pragma unroll
        for (int j = 0; j < 7; j++) {
            if (j < 7 - i) {
                unsigned long long lo = (k[j] < k[j + 1]) ? k[j] : k[j + 1];
                unsigned long long hi = (k[j] < k[j + 1]) ? k[j + 1] : k[j];
                k[j] = lo; k[j + 1] = hi;
            }
        }

#pragma unroll
    for (int off = 16; off; off >>= 1) sum += __shfl_down_sync(0xffffffffu, sum, off);
    if (lane == 0) sred[wid] = sum;
    __syncthreads();
    if (t == 0) {
        float s = 0.f;
        for (int i = 0; i < 16; i++) s += sred[i];
        g_T[w] = s;
        float f = 0.f;
        for (int q = 0; q < RRN; q++) f += row[q];
        g_f10[w] = f;
    }

    for (int r = 0; r < RRN; r++) {
        unsigned long long m = k[0];
#pragma unroll
        for (int off = 16; off; off >>= 1) {
            unsigned long long o = __shfl_down_sync(0xffffffffu, m, off);
            if (o < m) m = o;
        }
        if (lane == 0) swin[wid] = m;
        __syncthreads();
        if (t < 16) {
            unsigned long long mm = swin[t];
#pragma unroll
            for (int off = 8; off; off >>= 1) {
                unsigned long long o = __shfl_down_sync(0x0000ffffu, mm, off);
                if (o < mm) mm = o;
            }
            if (t == 0) {
                winner = mm;
                g_nid[w * RRN + r]  = __uint_as_float((unsigned)(mm >> 32));
                g_nidx[w * RRN + r] = (int)(mm & 0xffffffffu);
            }
        }
        __syncthreads();
        if (k[0] == winner) {
#pragma unroll
            for (int i = 0; i < 7; i++) k[i] = k[i + 1];
            k[7] = 0xFFFFFFFFFFFFFFFFULL;
        }
    }
}

// ---------------- K6: stats + relation MLP -> i_w, onw ----------------
__global__ __launch_bounds__(1024) void k_small(const float* __restrict__ Wr1, const float* __restrict__ br1,
                                                const float* __restrict__ Wr2, const float* __restrict__ br2) {
    __shared__ float sT[32], sf10[32];
    __shared__ float snid[32][10];
    __shared__ int   sidx[32][10];
    __shared__ float scn[32][32];
    __shared__ float snod[32][10];
    int t = threadIdx.x;

    if (t < 32) { sT[t] = g_T[t]; sf10[t] = g_f10[t]; }
    if (t < 320) { int i = t / 10, kk = t % 10; snid[i][kk] = g_nid[t]; sidx[i][kk] = g_nidx[t]; }
    __syncthreads();

    {
        int i = t >> 5, j = t & 31;
        float s = 0.f;
        for (int kk = 0; kk < 10; kk++) s += g_dis[j * QN + sidx[i][kk]];
        scn[i][j] = s;
    }
    if (t < 320) {
        int i = t / 10, kk = t % 10;
        int q = sidx[i][kk];
        float s = 0.f;
        for (int j = 0; j < 32; j++) s += g_dis[j * QN + q];
        snod[i][kk] = (s - snid[i][kk]) * (1.0f / 31.0f);
    }
    __syncthreads();

    if (t < 32) {
        int i = t;
        float nsum = 0.f;
        for (int kk = 0; kk < 10; kk++) nsum += snid[i][kk];
        float oid = (sT[i] - nsum) * (1.0f / (float)(QN - RRN));
        float sa = 0.f;
        for (int j = 0; j < i; j++) sa += sT[j] - scn[i][j];
        float sb = 0.f;
        for (int j = i + 1; j < 32; j++) sb += sT[j] - sf10[j];
        float ood = (sa + sb) * (1.0f / (float)((WAYN - 1) * (QN - RRN)));

        float rin[22];
        for (int kk = 0; kk < 10; kk++) { rin[kk] = snid[i][kk]; rin[10 + kk] = snod[i][kk]; }
        rin[20] = oid; rin[21] = ood;

        float hr[10];
        for (int r = 0; r < 10; r++) {
            float a = br1[r];
            for (int d = 0; d < 22; d++) a = fmaf(rin[d], Wr1[d * 10 + r], a);
            hr[r] = fmaxf(a, 0.f);
        }
        float orr[11];
        for (int j = 0; j < 11; j++) {
            float a = br2[j];
            for (int r = 0; r < 10; r++) a = fmaf(hr[r], Wr2[r * 11 + j], a);
            orr[j] = a;
        }
        float m = orr[0];
        for (int kk = 1; kk < 10; kk++) m = fmaxf(m, orr[kk]);
        float e[10], se = 0.f;
        for (int kk = 0; kk < 10; kk++) { e[kk] = expf(orr[kk] - m); se += e[kk]; }
        for (int kk = 0; kk < 10; kk++) g_iw[i * 10 + kk] = e[kk] / se;
        g_onw[i] = 1.f / (1.f + expf(-orr[10]));
    }
}

// ---------------- K7: weighted query + test proto (transposed) + norm/scale ----------------
__global__ void k_wdq(const float* __restrict__ dq) {
    int w = blockIdx.x, t = threadIdx.x;
    __shared__ float iw[10];
    __shared__ int   id[10];
    __shared__ float red[256];
    if (t < 10) { iw[t] = g_iw[w * 10 + t]; id[t] = g_nidx[w * 10 + t]; }
    __syncthreads();
    float onw = g_onw[w];
    float om  = 1.f - onw;
    float4 wd = make_float4(0.f, 0.f, 0.f, 0.f);
#pragma unroll
    for (int kk = 0; kk < 10; kk++) {
        float4 qv = *((const float4*)(dq + (size_t)id[kk] * DIMN) + t);
        float wk = iw[kk];
        wd.x = fmaf(wk, qv.x, wd.x); wd.y = fmaf(wk, qv.y, wd.y);
        wd.z = fmaf(wk, qv.z, wd.z); wd.w = fmaf(wk, qv.w, wd.w);
    }
    float4 pv = *((const float4*)(g_protos + w * DIMN) + t);
    float4 tm;
    tm.x = pv.x * onw + wd.x * om;
    tm.y = pv.y * onw + wd.y * om;
    tm.z = pv.z * onw + wd.z * om;
    tm.w = pv.w * onw + wd.w * om;
    int d0 = t * 4;
    g_tmpT[(d0 + 0) * WAYN + w] = tm.x;
    g_tmpT[(d0 + 1) * WAYN + w] = tm.y;
    g_tmpT[(d0 + 2) * WAYN + w] = tm.z;
    g_tmpT[(d0 + 3) * WAYN + w] = tm.w;

    red[t] = tm.x * tm.x + tm.y * tm.y + tm.z * tm.z + tm.w * tm.w;
    if (t < 96) red[160 + t] = 0.f;
    __syncthreads();
    for (int o = 128; o; o >>= 1) { if (t < o) red[t] += red[t + o]; __syncthreads(); }
    if (t == 0) {
        float nt = sqrtf(red[0]);
        g_tn[w] = nt;
        g_st[w] = expmap_scale(nt, g_c[w]);
    }
}

// ---------------- launch ----------------
extern "C" void kernel_launch(void* const* d_in, const int* in_sizes, int n_in,
                              void* d_out, int out_size) {
    const float* ds  = (const float*)d_in[0];
    const float* dq  = (const float*)d_in[1];
    const float* W1  = (const float*)d_in[2];
    const float* b1  = (const float*)d_in[3];
    const float* W2  = (const float*)d_in[4];
    const float* b2  = (const float*)d_in[5];
    const float* W3  = (const float*)d_in[6];
    const float* b3  = (const float*)d_in[7];
    const float* Wr1 = (const float*)d_in[8];
    const float* br1 = (const float*)d_in[9];
    const float* Wr2 = (const float*)d_in[10];
    const float* br2 = (const float*)d_in[11];
    float* out = (float*)d_out;

    k_pre<<<32 + NPART, 256>>>(ds, dq);
    k_ctrl<<<32, 256>>>(W1, b1, W2, b2, W3, b3);
    k_gemm_dist<<<256, 256>>>(dq, out, 0);
    k_topk<<<32, 512>>>();
    k_small<<<1, 1024>>>(Wr1, br1, Wr2, br2);
    k_wdq<<<32, 160>>>(dq);
    k_gemm_dist<<<256, 256>>>(dq, out, 1);
}